// round 12
// baseline (speedup 1.0000x reference)
#include <cuda_runtime.h>
#include <cuda_bf16.h>
#include <math.h>
#include <stdint.h>

// Problem dims
#define BB 2048
#define TT 64
#define DD 512
#define SS 256
#define PP 11
#define HH1 384
#define NCAT 1152   // HH1 + 3*SS

// Scratch layout (float units) in one __device__ array
#define OFF_F    ((size_t)0)                          // [B*T, NCAT] (b-major)
#define SZ_F     ((size_t)BB * TT * NCAT)
#define OFF_ZH   (OFF_F + SZ_F)                       // [B, NCAT]
#define SZ_ZH    ((size_t)BB * NCAT)
#define OFF_GUM  (OFF_ZH + SZ_ZH)                     // [B*T*P] gumbel noise
#define SZ_GUM   ((size_t)BB * TT * PP)
#define OFF_WPOS (OFF_GUM + SZ_GUM)                   // [3*S]
#define SZ_WPOS  ((size_t)768)
#define OFF_BF   (OFF_WPOS + SZ_WPOS)                 // [NCAT] bias for F
#define SZ_BF    ((size_t)1280)
#define OFF_BZH  (OFF_BF + SZ_BF)                     // [NCAT] bias for Zh
#define SZ_BZH   ((size_t)1280)
#define OFF_WFHI (OFF_BZH + SZ_BZH)                   // u32 [NCAT][DD/2]
#define SZ_WFHI  ((size_t)NCAT * DD / 2)
#define OFF_WFLO (OFF_WFHI + SZ_WFHI)
#define OFF_WHHI (OFF_WFLO + SZ_WFHI)                 // u32 [NCAT][SS/2]
#define SZ_WHHI  ((size_t)NCAT * SS / 2)
#define OFF_WHLO (OFF_WHHI + SZ_WHHI)
#define OFF_HHI  (OFF_WHLO + SZ_WHHI)                 // u32 [B][SS/2] bf16 pairs
#define SZ_HHI   ((size_t)BB * SS / 2)
#define OFF_HLO  (OFF_HHI + SZ_HHI)
#define SCRATCH_TOTAL (OFF_HLO + SZ_HHI)

__device__ float g_scratch[SCRATCH_TOTAL];

// ---------------------------------------------------------------------------
__device__ __forceinline__ void split_pack(float x, float y,
                                           unsigned& hi, unsigned& lo) {
    __nv_bfloat162 h2 = __float22bfloat162_rn(make_float2(x, y));
    float rx = x - __bfloat162float(h2.x);
    float ry = y - __bfloat162float(h2.y);
    __nv_bfloat162 l2 = __float22bfloat162_rn(make_float2(rx, ry));
    hi = reinterpret_cast<unsigned&>(h2);
    lo = reinterpret_cast<unsigned&>(l2);
}

// ---------------------------------------------------------------------------
// Pack kernel: pre-split fused weights to bf16 hi/lo, biases, wpos, h init
// ---------------------------------------------------------------------------
__global__ void pack_kernel(const float* __restrict__ W1,
                            const float* __restrict__ b1,
                            const float* __restrict__ W_ih,
                            const float* __restrict__ b_ih,
                            const float* __restrict__ W_hh,
                            const float* __restrict__ b_hh,
                            const float* __restrict__ h0,
                            unsigned* __restrict__ Wfhi,
                            unsigned* __restrict__ Wflo,
                            unsigned* __restrict__ Whhi,
                            unsigned* __restrict__ Whlo,
                            float* __restrict__ bf,
                            float* __restrict__ bzh,
                            unsigned* __restrict__ h_hi,
                            unsigned* __restrict__ h_lo,
                            float* __restrict__ wpos)
{
    int i = blockIdx.x * blockDim.x + threadIdx.x;
    if (i < NCAT * DD / 2) {
        int n = i / (DD / 2), kp = i % (DD / 2);
        int k0 = 2 * kp;
        float v0, v1;
        if (n < HH1) {
            v0 = W1[n * (DD + SS) + k0];
            v1 = W1[n * (DD + SS) + k0 + 1];
        } else {
            v0 = W_ih[(size_t)(n - HH1) * (DD + 1) + k0];
            v1 = W_ih[(size_t)(n - HH1) * (DD + 1) + k0 + 1];
        }
        unsigned hi, lo;
        split_pack(v0, v1, hi, lo);
        Wfhi[i] = hi; Wflo[i] = lo;
    }
    if (i < NCAT * SS / 2) {
        int n = i / (SS / 2), kp = i % (SS / 2);
        int k0 = 2 * kp;
        float v0, v1;
        if (n < HH1) {
            v0 = W1[n * (DD + SS) + DD + k0];
            v1 = W1[n * (DD + SS) + DD + k0 + 1];
        } else {
            v0 = W_hh[(n - HH1) * SS + k0];
            v1 = W_hh[(n - HH1) * SS + k0 + 1];
        }
        unsigned hi, lo;
        split_pack(v0, v1, hi, lo);
        Whhi[i] = hi; Whlo[i] = lo;
    }
    if (i < NCAT) {
        bf[i]  = (i < HH1) ? b1[i] : b_ih[i - HH1];
        bzh[i] = (i < HH1) ? 0.0f : b_hh[i - HH1];
    }
    if (i < BB * SS) {
        float v = h0[i % SS];
        __nv_bfloat16 bh = __float2bfloat16(v);
        ((__nv_bfloat16*)h_hi)[i] = bh;
        ((__nv_bfloat16*)h_lo)[i] = __float2bfloat16(v - __bfloat162float(bh));
    }
    if (i < 3 * SS) wpos[i] = W_ih[(size_t)i * (DD + 1) + DD];
}

// ---------------------------------------------------------------------------
// Gumbel precompute
// ---------------------------------------------------------------------------
__global__ void gumbel_kernel(const float* __restrict__ u,
                              float* __restrict__ gum)
{
    int i = blockIdx.x * blockDim.x + threadIdx.x;
    if (i < BB * TT * PP) {
        float uu = u[i];
        gum[i] = -logf(-logf(uu + 1e-20f) + 1e-20f);
    }
}

// ---------------------------------------------------------------------------
__device__ __forceinline__ void mma16(float* c, const unsigned* a,
                                      unsigned b0, unsigned b1) {
    asm volatile(
        "mma.sync.aligned.m16n8k16.row.col.f32.bf16.bf16.f32 "
        "{%0,%1,%2,%3}, {%4,%5,%6,%7}, {%8,%9}, {%0,%1,%2,%3};\n"
        : "+f"(c[0]), "+f"(c[1]), "+f"(c[2]), "+f"(c[3])
        : "r"(a[0]), "r"(a[1]), "r"(a[2]), "r"(a[3]), "r"(b0), "r"(b1));
}

#define KW 12   // padded u32 k-stride (8 used) -> conflict-free fragment loads

// ---------------------------------------------------------------------------
// Big F GEMM (R11, measured ~880us): symmetric 3-pass, double-buffered.
// BM=BN=128, BK=16, 8 warps (4m x 2n).
// ---------------------------------------------------------------------------
__global__ void __launch_bounds__(256, 2)
gemm_f(const float* __restrict__ A,
       const unsigned* __restrict__ Bhi,
       const unsigned* __restrict__ Blo,
       const float* __restrict__ bias,
       float* __restrict__ C)
{
    const int K = DD, N = NCAT;
    __shared__ unsigned As_hi[2][128][KW];
    __shared__ unsigned As_lo[2][128][KW];
    __shared__ unsigned Bs_hi[2][128][KW];
    __shared__ unsigned Bs_lo[2][128][KW];

    const int tid  = threadIdx.x;
    const int warp = tid >> 5, lane = tid & 31;
    const int g = lane >> 2, t = lane & 3;
    const int wm = warp >> 1, wn = warp & 1;   // 4 x 2 warp grid

    const int n0 = blockIdx.x * 128;
    const int m0 = blockIdx.y * 128;

    const int lrowA = tid >> 2;
    const int lcolA = (tid & 3) * 4;
    const int lc2   = (tid & 3) * 2;
    const int lrowB = tid >> 1;
    const int lcolB = (tid & 1) * 4;
    const int Khalf = K >> 1;

    float acc[2][8][4];
#pragma unroll
    for (int mt = 0; mt < 2; mt++)
#pragma unroll
        for (int nt = 0; nt < 8; nt++)
#pragma unroll
            for (int r = 0; r < 4; r++) acc[mt][nt][r] = 0.0f;

    {
#pragma unroll
        for (int i = 0; i < 2; i++) {
            float4 v = *(const float4*)(A + (size_t)(m0 + lrowA + i * 64) * K + lcolA);
            int row = lrowA + i * 64;
            unsigned h0, l0, h1, l1;
            split_pack(v.x, v.y, h0, l0);
            split_pack(v.z, v.w, h1, l1);
            As_hi[0][row][lc2] = h0; As_hi[0][row][lc2 + 1] = h1;
            As_lo[0][row][lc2] = l0; As_lo[0][row][lc2 + 1] = l1;
        }
        *(uint4*)&Bs_hi[0][lrowB][lcolB] =
            *(const uint4*)(Bhi + (size_t)(n0 + lrowB) * Khalf + lcolB);
        *(uint4*)&Bs_lo[0][lrowB][lcolB] =
            *(const uint4*)(Blo + (size_t)(n0 + lrowB) * Khalf + lcolB);
    }

    int cur = 0;
    for (int k0 = 0; k0 < K; k0 += 16) {
        __syncthreads();
        const bool hasNext = (k0 + 16 < K);

        float4 na[2];
        uint4 nbh, nbl;
        if (hasNext) {
            int koff = k0 + 16;
#pragma unroll
            for (int i = 0; i < 2; i++)
                na[i] = *(const float4*)(A + (size_t)(m0 + lrowA + i * 64) * K + koff + lcolA);
            nbh = *(const uint4*)(Bhi + (size_t)(n0 + lrowB) * Khalf + koff / 2 + lcolB);
            nbl = *(const uint4*)(Blo + (size_t)(n0 + lrowB) * Khalf + koff / 2 + lcolB);
        }

        unsigned ah[2][4], al[2][4];
#pragma unroll
        for (int mt = 0; mt < 2; mt++) {
            int mb = wm * 32 + mt * 16;
            ah[mt][0] = As_hi[cur][mb + g    ][t];
            ah[mt][1] = As_hi[cur][mb + g + 8][t];
            ah[mt][2] = As_hi[cur][mb + g    ][t + 4];
            ah[mt][3] = As_hi[cur][mb + g + 8][t + 4];
            al[mt][0] = As_lo[cur][mb + g    ][t];
            al[mt][1] = As_lo[cur][mb + g + 8][t];
            al[mt][2] = As_lo[cur][mb + g    ][t + 4];
            al[mt][3] = As_lo[cur][mb + g + 8][t + 4];
        }
#pragma unroll
        for (int nt = 0; nt < 8; nt++) {
            int nb = wn * 64 + nt * 8;
            unsigned bh0 = Bs_hi[cur][nb + g][t];
            unsigned bh1 = Bs_hi[cur][nb + g][t + 4];
            unsigned bl0 = Bs_lo[cur][nb + g][t];
            unsigned bl1 = Bs_lo[cur][nb + g][t + 4];
#pragma unroll
            for (int mt = 0; mt < 2; mt++) {
                mma16(acc[mt][nt], al[mt], bh0, bh1);
                mma16(acc[mt][nt], ah[mt], bl0, bl1);
                mma16(acc[mt][nt], ah[mt], bh0, bh1);
            }
        }

        if (hasNext) {
            int nxt = cur ^ 1;
#pragma unroll
            for (int i = 0; i < 2; i++) {
                int row = lrowA + i * 64;
                unsigned h0, l0, h1, l1;
                split_pack(na[i].x, na[i].y, h0, l0);
                split_pack(na[i].z, na[i].w, h1, l1);
                As_hi[nxt][row][lc2] = h0; As_hi[nxt][row][lc2 + 1] = h1;
                As_lo[nxt][row][lc2] = l0; As_lo[nxt][row][lc2 + 1] = l1;
            }
            *(uint4*)&Bs_hi[nxt][lrowB][lcolB] = nbh;
            *(uint4*)&Bs_lo[nxt][lrowB][lcolB] = nbl;
        }
        cur ^= 1;
    }

#pragma unroll
    for (int mt = 0; mt < 2; mt++) {
        int r0 = m0 + wm * 32 + mt * 16 + g;
#pragma unroll
        for (int nt = 0; nt < 8; nt++) {
            int col = n0 + wn * 64 + nt * 8 + 2 * t;
            float bv0 = bias[col], bv1 = bias[col + 1];
            float2 v;
            v.x = acc[mt][nt][0] + bv0; v.y = acc[mt][nt][1] + bv1;
            *(float2*)&C[(size_t)r0 * N + col] = v;
            v.x = acc[mt][nt][2] + bv0; v.y = acc[mt][nt][3] + bv1;
            *(float2*)&C[(size_t)(r0 + 8) * N + col] = v;
        }
    }
}

// ---------------------------------------------------------------------------
// Recurrent Zh GEMM: BM=128 x BN=64 -> grid (18,16)=288 blocks = 2 CTAs/SM
// for latency hiding (old 144-block shape ran at occ 12%, issue 16%).
// 8 warps as 4m x 2n, warp tile 32x32 (2m x 4n frags). Symmetric 3-pass,
// double-buffered, one sync per k16. smem 36KB, ~90 regs -> 2 CTAs resident.
// ---------------------------------------------------------------------------
__global__ void __launch_bounds__(256, 2)
gemm_zh(const unsigned* __restrict__ Ahi,
        const unsigned* __restrict__ Alo,
        const unsigned* __restrict__ Bhi,
        const unsigned* __restrict__ Blo,
        const float* __restrict__ bias,
        float* __restrict__ C)
{
    __shared__ unsigned As_hi[2][128][KW];
    __shared__ unsigned As_lo[2][128][KW];
    __shared__ unsigned Bs_hi[2][64][KW];
    __shared__ unsigned Bs_lo[2][64][KW];

    const int tid  = threadIdx.x;
    const int warp = tid >> 5, lane = tid & 31;
    const int g = lane >> 2, t = lane & 3;
    const int wm = warp >> 1, wn = warp & 1;   // 4 x 2 warp grid

    const int n0 = blockIdx.x * 64;
    const int m0 = blockIdx.y * 128;

    const int lrowA = tid >> 1;          // 0..127, uint4 per thread
    const int lcolA = (tid & 1) * 4;
    const int lrowB = tid >> 2;          // 0..63, uint2 per thread
    const int lcolB = (tid & 3) * 2;
    const int Khalf = SS / 2;            // 128 u32 per row

    float acc[2][4][4];
#pragma unroll
    for (int mt = 0; mt < 2; mt++)
#pragma unroll
        for (int nt = 0; nt < 4; nt++)
#pragma unroll
            for (int r = 0; r < 4; r++) acc[mt][nt][r] = 0.0f;

    *(uint4*)&As_hi[0][lrowA][lcolA] = *(const uint4*)(Ahi + (size_t)(m0 + lrowA) * Khalf + lcolA);
    *(uint4*)&As_lo[0][lrowA][lcolA] = *(const uint4*)(Alo + (size_t)(m0 + lrowA) * Khalf + lcolA);
    *(uint2*)&Bs_hi[0][lrowB][lcolB] = *(const uint2*)(Bhi + (size_t)(n0 + lrowB) * Khalf + lcolB);
    *(uint2*)&Bs_lo[0][lrowB][lcolB] = *(const uint2*)(Blo + (size_t)(n0 + lrowB) * Khalf + lcolB);

    int cur = 0;
    for (int k0 = 0; k0 < SS; k0 += 16) {
        __syncthreads();
        const bool hasNext = (k0 + 16 < SS);

        uint4 nah, nal;
        uint2 nbh, nbl;
        if (hasNext) {
            int koff = (k0 + 16) / 2;
            nah = *(const uint4*)(Ahi + (size_t)(m0 + lrowA) * Khalf + koff + lcolA);
            nal = *(const uint4*)(Alo + (size_t)(m0 + lrowA) * Khalf + koff + lcolA);
            nbh = *(const uint2*)(Bhi + (size_t)(n0 + lrowB) * Khalf + koff + lcolB);
            nbl = *(const uint2*)(Blo + (size_t)(n0 + lrowB) * Khalf + koff + lcolB);
        }

        unsigned ah[2][4], al[2][4];
#pragma unroll
        for (int mt = 0; mt < 2; mt++) {
            int mb = wm * 32 + mt * 16;
            ah[mt][0] = As_hi[cur][mb + g    ][t];
            ah[mt][1] = As_hi[cur][mb + g + 8][t];
            ah[mt][2] = As_hi[cur][mb + g    ][t + 4];
            ah[mt][3] = As_hi[cur][mb + g + 8][t + 4];
            al[mt][0] = As_lo[cur][mb + g    ][t];
            al[mt][1] = As_lo[cur][mb + g + 8][t];
            al[mt][2] = As_lo[cur][mb + g    ][t + 4];
            al[mt][3] = As_lo[cur][mb + g + 8][t + 4];
        }
#pragma unroll
        for (int nt = 0; nt < 4; nt++) {
            int nb = wn * 32 + nt * 8;
            unsigned bh0 = Bs_hi[cur][nb + g][t];
            unsigned bh1 = Bs_hi[cur][nb + g][t + 4];
            unsigned bl0 = Bs_lo[cur][nb + g][t];
            unsigned bl1 = Bs_lo[cur][nb + g][t + 4];
#pragma unroll
            for (int mt = 0; mt < 2; mt++) {
                mma16(acc[mt][nt], al[mt], bh0, bh1);
                mma16(acc[mt][nt], ah[mt], bl0, bl1);
                mma16(acc[mt][nt], ah[mt], bh0, bh1);
            }
        }

        if (hasNext) {
            int nxt = cur ^ 1;
            *(uint4*)&As_hi[nxt][lrowA][lcolA] = nah;
            *(uint4*)&As_lo[nxt][lrowA][lcolA] = nal;
            *(uint2*)&Bs_hi[nxt][lrowB][lcolB] = nbh;
            *(uint2*)&Bs_lo[nxt][lrowB][lcolB] = nbl;
        }
        cur ^= 1;
    }

#pragma unroll
    for (int mt = 0; mt < 2; mt++) {
        int r0 = m0 + wm * 32 + mt * 16 + g;
#pragma unroll
        for (int nt = 0; nt < 4; nt++) {
            int col = n0 + wn * 32 + nt * 8 + 2 * t;
            float bv0 = bias[col], bv1 = bias[col + 1];
            float2 v;
            v.x = acc[mt][nt][0] + bv0; v.y = acc[mt][nt][1] + bv1;
            *(float2*)&C[(size_t)r0 * NCAT + col] = v;
            v.x = acc[mt][nt][2] + bv0; v.y = acc[mt][nt][3] + bv1;
            *(float2*)&C[(size_t)(r0 + 8) * NCAT + col] = v;
        }
    }
}

// ---------------------------------------------------------------------------
// Per-step fusion (R11, measured 14.4us with better occ): block-per-row,
// slim registers, precomputed gumbel, bf16 hold, MUFU fast-exp gates.
// ---------------------------------------------------------------------------
__global__ void __launch_bounds__(256)
step_kernel(int t,
            const float* __restrict__ gum,
            const float* __restrict__ W2,
            const float* __restrict__ b2,
            const float* __restrict__ temp_ptr,
            const float* __restrict__ wpos,
            const float* __restrict__ F,
            const float* __restrict__ Zh,
            unsigned* __restrict__ h_hi,
            unsigned* __restrict__ h_lo,
            float* __restrict__ out_pos,
            float* __restrict__ out_states,
            float* __restrict__ out_hfinal)
{
    const int b = blockIdx.x;
    const int tid = threadIdx.x;
    const int warp = tid >> 5, lane = tid & 31;
    const size_t bt = (size_t)b * TT + t;

    __shared__ float sh_hidden[HH1];
    __shared__ float sh_logits[PP];
    __shared__ float sh_pos;

    const float* Frow = F + bt * NCAT;
    const float* Zrow = Zh + (size_t)b * NCAT;

    const int j = tid;   // 0..255 == SS
    __nv_bfloat16 hold_hi = ((const __nv_bfloat16*)h_hi)[(size_t)b * SS + j];
    __nv_bfloat16 hold_lo = ((const __nv_bfloat16*)h_lo)[(size_t)b * SS + j];
    float f_r = Frow[HH1 + j];
    float f_z = Frow[HH1 + SS + j];
    float f_n = Frow[HH1 + 2 * SS + j];
    float z_r = Zrow[HH1 + j];
    float z_z = Zrow[HH1 + SS + j];
    float z_n = Zrow[HH1 + 2 * SS + j];
    float wp_r = wpos[j];
    float wp_z = wpos[SS + j];
    float wp_n = wpos[2 * SS + j];

    float2 hf2, hz2;
    if (tid < 192) {
        hf2 = ((const float2*)Frow)[tid];
        hz2 = ((const float2*)Zrow)[tid];
    }

    float gv = 0.0f, temp = 1.0f;
    if (warp == 0) {
        temp = *temp_ptr;
        if (lane < PP) gv = gum[bt * PP + lane];
    }

    if (tid < 192) {
        float2 r;
        r.x = fmaxf(hf2.x + hz2.x, 0.0f);
        r.y = fmaxf(hf2.y + hz2.y, 0.0f);
        ((float2*)sh_hidden)[tid] = r;
    }
    __syncthreads();

    {
        const float4* h4 = (const float4*)sh_hidden;
        const float4* W2a = (const float4*)(W2 + warp * HH1);
        float s = 0.0f;
#pragma unroll
        for (int i = 0; i < 3; i++) {
            float4 w = W2a[lane + 32 * i], hh = h4[lane + 32 * i];
            s = fmaf(w.x, hh.x, s); s = fmaf(w.y, hh.y, s);
            s = fmaf(w.z, hh.z, s); s = fmaf(w.w, hh.w, s);
        }
#pragma unroll
        for (int off = 16; off > 0; off >>= 1)
            s += __shfl_xor_sync(0xffffffffu, s, off);
        if (lane == 0) sh_logits[warp] = s + b2[warp];

        if (warp < 3) {
            const float4* W2b = (const float4*)(W2 + (warp + 8) * HH1);
            float s2 = 0.0f;
#pragma unroll
            for (int i = 0; i < 3; i++) {
                float4 w = W2b[lane + 32 * i], hh = h4[lane + 32 * i];
                s2 = fmaf(w.x, hh.x, s2); s2 = fmaf(w.y, hh.y, s2);
                s2 = fmaf(w.z, hh.z, s2); s2 = fmaf(w.w, hh.w, s2);
            }
#pragma unroll
            for (int off = 16; off > 0; off >>= 1)
                s2 += __shfl_xor_sync(0xffffffffu, s2, off);
            if (lane == 0) sh_logits[warp + 8] = s2 + b2[warp + 8];
        }
    }
    __syncthreads();

    if (warp == 0) {
        float val = -INFINITY;
        if (lane < PP) val = (sh_logits[lane] + gv) / temp;
        float m = val;
#pragma unroll
        for (int off = 16; off > 0; off >>= 1)
            m = fmaxf(m, __shfl_xor_sync(0xffffffffu, m, off));
        float e = (lane < PP) ? __expf(val - m) : 0.0f;
        float s = e;
        float w = (lane < PP) ? e * (float)lane : 0.0f;
#pragma unroll
        for (int off = 16; off > 0; off >>= 1) {
            s += __shfl_xor_sync(0xffffffffu, s, off);
            w += __shfl_xor_sync(0xffffffffu, w, off);
        }
        if (lane == 0) {
            float pos = w / s;
            sh_pos = pos;
            out_pos[bt] = pos;
        }
    }
    __syncthreads();
    const float pos = sh_pos;

    float hold = __bfloat162float(hold_hi) + __bfloat162float(hold_lo);
    float gi_r = f_r + pos * wp_r;
    float gi_z = f_z + pos * wp_z;
    float gi_n = f_n + pos * wp_n;

    float r = 1.0f / (1.0f + __expf(-(gi_r + z_r)));
    float z = 1.0f / (1.0f + __expf(-(gi_z + z_z)));
    float xn = gi_n + r * z_n;
    float n = 1.0f - 2.0f / (__expf(2.0f * xn) + 1.0f);
    float hnew = (1.0f - z) * n + z * hold;

    {
        __nv_bfloat16 bh = __float2bfloat16(hnew);
        ((__nv_bfloat16*)h_hi)[(size_t)b * SS + j] = bh;
        ((__nv_bfloat16*)h_lo)[(size_t)b * SS + j] =
            __float2bfloat16(hnew - __bfloat162float(bh));
    }
    out_states[bt * SS + j] = hnew;
    if (t == TT - 1) out_hfinal[(size_t)b * SS + j] = hnew;
}

// ---------------------------------------------------------------------------
extern "C" void kernel_launch(void* const* d_in, const int* in_sizes, int n_in,
                              void* d_out, int out_size)
{
    const float* price = (const float*)d_in[0];
    const float* u     = (const float*)d_in[1];
    const float* W1    = (const float*)d_in[2];
    const float* b1    = (const float*)d_in[3];
    const float* W2    = (const float*)d_in[4];
    const float* b2    = (const float*)d_in[5];
    const float* temp  = (const float*)d_in[6];
    const float* W_ih  = (const float*)d_in[7];
    const float* b_ih  = (const float*)d_in[8];
    const float* W_hh  = (const float*)d_in[9];
    const float* b_hh  = (const float*)d_in[10];
    const float* h0    = (const float*)d_in[11];

    float* scratch = nullptr;
    cudaGetSymbolAddress((void**)&scratch, g_scratch);
    float* F      = scratch + OFF_F;
    float* Zh     = scratch + OFF_ZH;
    float* gum    = scratch + OFF_GUM;
    float* wpos   = scratch + OFF_WPOS;
    float* bf     = scratch + OFF_BF;
    float* bzh    = scratch + OFF_BZH;
    unsigned* Wfhi = (unsigned*)(scratch + OFF_WFHI);
    unsigned* Wflo = (unsigned*)(scratch + OFF_WFLO);
    unsigned* Whhi = (unsigned*)(scratch + OFF_WHHI);
    unsigned* Whlo = (unsigned*)(scratch + OFF_WHLO);
    unsigned* h_hi = (unsigned*)(scratch + OFF_HHI);
    unsigned* h_lo = (unsigned*)(scratch + OFF_HLO);

    float* out        = (float*)d_out;
    float* out_pos    = out;                                  // [B, T]
    float* out_states = out + (size_t)BB * TT;                // [B, T, S]
    float* out_hf     = out_states + (size_t)BB * TT * SS;    // [B, S]

    // 1. pack + gumbel precompute
    pack_kernel<<<(BB * SS + 255) / 256, 256>>>(W1, b1, W_ih, b_ih, W_hh, b_hh,
                                                h0, Wfhi, Wflo, Whhi, Whlo,
                                                bf, bzh, h_hi, h_lo, wpos);
    gumbel_kernel<<<(BB * TT * PP + 255) / 256, 256>>>(u, gum);

    // 2. big parallel GEMM: F[B*T, NCAT] = feats @ Wf^T + bf
    {
        dim3 grid(NCAT / 128, (BB * TT) / 128);   // (9, 1024)
        gemm_f<<<grid, 256>>>(price, Wfhi, Wflo, bf, F);
    }

    // 3. sequential recurrence: 128x64-tile Zh (288 blocks, 2 CTA/SM) + step
    for (int t = 0; t < TT; t++) {
        dim3 grid(NCAT / 64, BB / 128);           // (18, 16) = 288 blocks
        gemm_zh<<<grid, 256>>>(h_hi, h_lo, Whhi, Whlo, bzh, Zh);
        step_kernel<<<BB, 256>>>(t, gum, W2, b2, temp, wpos,
                                 F, Zh, h_hi, h_lo,
                                 out_pos, out_states, out_hf);
    }
}

// round 13
// speedup vs baseline: 1.0923x; 1.0923x over previous
#include <cuda_runtime.h>
#include <cuda_bf16.h>
#include <math.h>
#include <stdint.h>

// Problem dims
#define BB 2048
#define TT 64
#define DD 512
#define SS 256
#define PP 11
#define HH1 384
#define NCAT 1152   // HH1 + 3*SS

// Scratch layout (float units) in one __device__ array
#define OFF_F    ((size_t)0)                          // [B*T, NCAT] (b-major)
#define SZ_F     ((size_t)BB * TT * NCAT)
#define OFF_ZH0  (OFF_F + SZ_F)                       // [B, NCAT] k-half 0
#define SZ_ZH    ((size_t)BB * NCAT)
#define OFF_ZH1  (OFF_ZH0 + SZ_ZH)                    // [B, NCAT] k-half 1
#define OFF_GUM  (OFF_ZH1 + SZ_ZH)                    // [B*T*P] gumbel noise
#define SZ_GUM   ((size_t)BB * TT * PP)
#define OFF_WPOS (OFF_GUM + SZ_GUM)                   // [3*S]
#define SZ_WPOS  ((size_t)768)
#define OFF_BF   (OFF_WPOS + SZ_WPOS)                 // [NCAT] bias for F
#define SZ_BF    ((size_t)1280)
#define OFF_BZH  (OFF_BF + SZ_BF)                     // [NCAT] bias for Zh
#define SZ_BZH   ((size_t)1280)
#define OFF_WFHI (OFF_BZH + SZ_BZH)                   // u32 [NCAT][DD/2]
#define SZ_WFHI  ((size_t)NCAT * DD / 2)
#define OFF_WFLO (OFF_WFHI + SZ_WFHI)
#define OFF_WHHI (OFF_WFLO + SZ_WFHI)                 // u32 [NCAT][SS/2]
#define SZ_WHHI  ((size_t)NCAT * SS / 2)
#define OFF_WHLO (OFF_WHHI + SZ_WHHI)
#define OFF_HHI  (OFF_WHLO + SZ_WHHI)                 // u32 [B][SS/2] bf16 pairs
#define SZ_HHI   ((size_t)BB * SS / 2)
#define OFF_HLO  (OFF_HHI + SZ_HHI)
#define SCRATCH_TOTAL (OFF_HLO + SZ_HHI)

__device__ float g_scratch[SCRATCH_TOTAL];

// ---------------------------------------------------------------------------
__device__ __forceinline__ void split_pack(float x, float y,
                                           unsigned& hi, unsigned& lo) {
    __nv_bfloat162 h2 = __float22bfloat162_rn(make_float2(x, y));
    float rx = x - __bfloat162float(h2.x);
    float ry = y - __bfloat162float(h2.y);
    __nv_bfloat162 l2 = __float22bfloat162_rn(make_float2(rx, ry));
    hi = reinterpret_cast<unsigned&>(h2);
    lo = reinterpret_cast<unsigned&>(l2);
}

// ---------------------------------------------------------------------------
// Pack kernel: pre-split fused weights to bf16 hi/lo, biases, wpos, h init
// ---------------------------------------------------------------------------
__global__ void pack_kernel(const float* __restrict__ W1,
                            const float* __restrict__ b1,
                            const float* __restrict__ W_ih,
                            const float* __restrict__ b_ih,
                            const float* __restrict__ W_hh,
                            const float* __restrict__ b_hh,
                            const float* __restrict__ h0,
                            unsigned* __restrict__ Wfhi,
                            unsigned* __restrict__ Wflo,
                            unsigned* __restrict__ Whhi,
                            unsigned* __restrict__ Whlo,
                            float* __restrict__ bf,
                            float* __restrict__ bzh,
                            unsigned* __restrict__ h_hi,
                            unsigned* __restrict__ h_lo,
                            float* __restrict__ wpos)
{
    int i = blockIdx.x * blockDim.x + threadIdx.x;
    if (i < NCAT * DD / 2) {
        int n = i / (DD / 2), kp = i % (DD / 2);
        int k0 = 2 * kp;
        float v0, v1;
        if (n < HH1) {
            v0 = W1[n * (DD + SS) + k0];
            v1 = W1[n * (DD + SS) + k0 + 1];
        } else {
            v0 = W_ih[(size_t)(n - HH1) * (DD + 1) + k0];
            v1 = W_ih[(size_t)(n - HH1) * (DD + 1) + k0 + 1];
        }
        unsigned hi, lo;
        split_pack(v0, v1, hi, lo);
        Wfhi[i] = hi; Wflo[i] = lo;
    }
    if (i < NCAT * SS / 2) {
        int n = i / (SS / 2), kp = i % (SS / 2);
        int k0 = 2 * kp;
        float v0, v1;
        if (n < HH1) {
            v0 = W1[n * (DD + SS) + DD + k0];
            v1 = W1[n * (DD + SS) + DD + k0 + 1];
        } else {
            v0 = W_hh[(n - HH1) * SS + k0];
            v1 = W_hh[(n - HH1) * SS + k0 + 1];
        }
        unsigned hi, lo;
        split_pack(v0, v1, hi, lo);
        Whhi[i] = hi; Whlo[i] = lo;
    }
    if (i < NCAT) {
        bf[i]  = (i < HH1) ? b1[i] : b_ih[i - HH1];
        bzh[i] = (i < HH1) ? 0.0f : b_hh[i - HH1];
    }
    if (i < BB * SS) {
        float v = h0[i % SS];
        __nv_bfloat16 bh = __float2bfloat16(v);
        ((__nv_bfloat16*)h_hi)[i] = bh;
        ((__nv_bfloat16*)h_lo)[i] = __float2bfloat16(v - __bfloat162float(bh));
    }
    if (i < 3 * SS) wpos[i] = W_ih[(size_t)i * (DD + 1) + DD];
}

// ---------------------------------------------------------------------------
// Gumbel precompute
// ---------------------------------------------------------------------------
__global__ void gumbel_kernel(const float* __restrict__ u,
                              float* __restrict__ gum)
{
    int i = blockIdx.x * blockDim.x + threadIdx.x;
    if (i < BB * TT * PP) {
        float uu = u[i];
        gum[i] = -logf(-logf(uu + 1e-20f) + 1e-20f);
    }
}

// ---------------------------------------------------------------------------
__device__ __forceinline__ void mma16(float* c, const unsigned* a,
                                      unsigned b0, unsigned b1) {
    asm volatile(
        "mma.sync.aligned.m16n8k16.row.col.f32.bf16.bf16.f32 "
        "{%0,%1,%2,%3}, {%4,%5,%6,%7}, {%8,%9}, {%0,%1,%2,%3};\n"
        : "+f"(c[0]), "+f"(c[1]), "+f"(c[2]), "+f"(c[3])
        : "r"(a[0]), "r"(a[1]), "r"(a[2]), "r"(a[3]), "r"(b0), "r"(b1));
}

#define KW 12   // padded u32 k-stride (8 used) -> conflict-free fragment loads

// ---------------------------------------------------------------------------
// Big F GEMM (R11, measured-best): symmetric 3-pass, double-buffered.
// BM=BN=128, BK=16, 8 warps (4m x 2n).
// ---------------------------------------------------------------------------
__global__ void __launch_bounds__(256, 2)
gemm_f(const float* __restrict__ A,
       const unsigned* __restrict__ Bhi,
       const unsigned* __restrict__ Blo,
       const float* __restrict__ bias,
       float* __restrict__ C)
{
    const int K = DD, N = NCAT;
    __shared__ unsigned As_hi[2][128][KW];
    __shared__ unsigned As_lo[2][128][KW];
    __shared__ unsigned Bs_hi[2][128][KW];
    __shared__ unsigned Bs_lo[2][128][KW];

    const int tid  = threadIdx.x;
    const int warp = tid >> 5, lane = tid & 31;
    const int g = lane >> 2, t = lane & 3;
    const int wm = warp >> 1, wn = warp & 1;   // 4 x 2 warp grid

    const int n0 = blockIdx.x * 128;
    const int m0 = blockIdx.y * 128;

    const int lrowA = tid >> 2;
    const int lcolA = (tid & 3) * 4;
    const int lc2   = (tid & 3) * 2;
    const int lrowB = tid >> 1;
    const int lcolB = (tid & 1) * 4;
    const int Khalf = K >> 1;

    float acc[2][8][4];
#pragma unroll
    for (int mt = 0; mt < 2; mt++)
#pragma unroll
        for (int nt = 0; nt < 8; nt++)
#pragma unroll
            for (int r = 0; r < 4; r++) acc[mt][nt][r] = 0.0f;

    {
#pragma unroll
        for (int i = 0; i < 2; i++) {
            float4 v = *(const float4*)(A + (size_t)(m0 + lrowA + i * 64) * K + lcolA);
            int row = lrowA + i * 64;
            unsigned h0, l0, h1, l1;
            split_pack(v.x, v.y, h0, l0);
            split_pack(v.z, v.w, h1, l1);
            As_hi[0][row][lc2] = h0; As_hi[0][row][lc2 + 1] = h1;
            As_lo[0][row][lc2] = l0; As_lo[0][row][lc2 + 1] = l1;
        }
        *(uint4*)&Bs_hi[0][lrowB][lcolB] =
            *(const uint4*)(Bhi + (size_t)(n0 + lrowB) * Khalf + lcolB);
        *(uint4*)&Bs_lo[0][lrowB][lcolB] =
            *(const uint4*)(Blo + (size_t)(n0 + lrowB) * Khalf + lcolB);
    }

    int cur = 0;
    for (int k0 = 0; k0 < K; k0 += 16) {
        __syncthreads();
        const bool hasNext = (k0 + 16 < K);

        float4 na[2];
        uint4 nbh, nbl;
        if (hasNext) {
            int koff = k0 + 16;
#pragma unroll
            for (int i = 0; i < 2; i++)
                na[i] = *(const float4*)(A + (size_t)(m0 + lrowA + i * 64) * K + koff + lcolA);
            nbh = *(const uint4*)(Bhi + (size_t)(n0 + lrowB) * Khalf + koff / 2 + lcolB);
            nbl = *(const uint4*)(Blo + (size_t)(n0 + lrowB) * Khalf + koff / 2 + lcolB);
        }

        unsigned ah[2][4], al[2][4];
#pragma unroll
        for (int mt = 0; mt < 2; mt++) {
            int mb = wm * 32 + mt * 16;
            ah[mt][0] = As_hi[cur][mb + g    ][t];
            ah[mt][1] = As_hi[cur][mb + g + 8][t];
            ah[mt][2] = As_hi[cur][mb + g    ][t + 4];
            ah[mt][3] = As_hi[cur][mb + g + 8][t + 4];
            al[mt][0] = As_lo[cur][mb + g    ][t];
            al[mt][1] = As_lo[cur][mb + g + 8][t];
            al[mt][2] = As_lo[cur][mb + g    ][t + 4];
            al[mt][3] = As_lo[cur][mb + g + 8][t + 4];
        }
#pragma unroll
        for (int nt = 0; nt < 8; nt++) {
            int nb = wn * 64 + nt * 8;
            unsigned bh0 = Bs_hi[cur][nb + g][t];
            unsigned bh1 = Bs_hi[cur][nb + g][t + 4];
            unsigned bl0 = Bs_lo[cur][nb + g][t];
            unsigned bl1 = Bs_lo[cur][nb + g][t + 4];
#pragma unroll
            for (int mt = 0; mt < 2; mt++) {
                mma16(acc[mt][nt], al[mt], bh0, bh1);
                mma16(acc[mt][nt], ah[mt], bl0, bl1);
                mma16(acc[mt][nt], ah[mt], bh0, bh1);
            }
        }

        if (hasNext) {
            int nxt = cur ^ 1;
#pragma unroll
            for (int i = 0; i < 2; i++) {
                int row = lrowA + i * 64;
                unsigned h0, l0, h1, l1;
                split_pack(na[i].x, na[i].y, h0, l0);
                split_pack(na[i].z, na[i].w, h1, l1);
                As_hi[nxt][row][lc2] = h0; As_hi[nxt][row][lc2 + 1] = h1;
                As_lo[nxt][row][lc2] = l0; As_lo[nxt][row][lc2 + 1] = l1;
            }
            *(uint4*)&Bs_hi[nxt][lrowB][lcolB] = nbh;
            *(uint4*)&Bs_lo[nxt][lrowB][lcolB] = nbl;
        }
        cur ^= 1;
    }

#pragma unroll
    for (int mt = 0; mt < 2; mt++) {
        int r0 = m0 + wm * 32 + mt * 16 + g;
#pragma unroll
        for (int nt = 0; nt < 8; nt++) {
            int col = n0 + wn * 64 + nt * 8 + 2 * t;
            float bv0 = bias[col], bv1 = bias[col + 1];
            float2 v;
            v.x = acc[mt][nt][0] + bv0; v.y = acc[mt][nt][1] + bv1;
            *(float2*)&C[(size_t)r0 * N + col] = v;
            v.x = acc[mt][nt][2] + bv0; v.y = acc[mt][nt][3] + bv1;
            *(float2*)&C[(size_t)(r0 + 8) * N + col] = v;
        }
    }
}

// ---------------------------------------------------------------------------
// Recurrent Zh GEMM, SPLIT-K: grid (9, 16, 2) = 288 blocks = 2 CTAs/SM.
// blockIdx.z selects K half (128 of 256). Tile 128x128 (measured-best shape),
// mainloop identical to R11. Half kr writes C + kr*B*NCAT; bias only on kr=0.
// step_kernel sums the two halves.
// ---------------------------------------------------------------------------
__global__ void __launch_bounds__(256, 2)
gemm_zh(const unsigned* __restrict__ Ahi,
        const unsigned* __restrict__ Alo,
        const unsigned* __restrict__ Bhi,
        const unsigned* __restrict__ Blo,
        const float* __restrict__ bias,
        float* __restrict__ C)
{
    __shared__ unsigned As_hi[2][128][KW];
    __shared__ unsigned As_lo[2][128][KW];
    __shared__ unsigned Bs_hi[2][128][KW];
    __shared__ unsigned Bs_lo[2][128][KW];

    const int tid  = threadIdx.x;
    const int warp = tid >> 5, lane = tid & 31;
    const int g = lane >> 2, t = lane & 3;
    const int wm = warp >> 1, wn = warp & 1;   // 4 x 2 warp grid

    const int n0 = blockIdx.x * 128;
    const int m0 = blockIdx.y * 128;
    const int kr = blockIdx.z;               // K half: 0 or 1

    const int lrow = tid >> 1;           // 0..127
    const int lcol = (tid & 1) * 4;
    const int Khalf = SS / 2;            // 128 u32 per operand row
    const int kbase = kr * 64;           // u32 offset of this K half
    const int KHALF_ITERS = 128;         // bf16 k-extent of this half

    float acc[2][8][4];
#pragma unroll
    for (int mt = 0; mt < 2; mt++)
#pragma unroll
        for (int nt = 0; nt < 8; nt++)
#pragma unroll
            for (int r = 0; r < 4; r++) acc[mt][nt][r] = 0.0f;

    *(uint4*)&As_hi[0][lrow][lcol] = *(const uint4*)(Ahi + (size_t)(m0 + lrow) * Khalf + kbase + lcol);
    *(uint4*)&As_lo[0][lrow][lcol] = *(const uint4*)(Alo + (size_t)(m0 + lrow) * Khalf + kbase + lcol);
    *(uint4*)&Bs_hi[0][lrow][lcol] = *(const uint4*)(Bhi + (size_t)(n0 + lrow) * Khalf + kbase + lcol);
    *(uint4*)&Bs_lo[0][lrow][lcol] = *(const uint4*)(Blo + (size_t)(n0 + lrow) * Khalf + kbase + lcol);

    int cur = 0;
    for (int k0 = 0; k0 < KHALF_ITERS; k0 += 16) {
        __syncthreads();
        const bool hasNext = (k0 + 16 < KHALF_ITERS);

        uint4 nah, nal, nbh, nbl;
        if (hasNext) {
            int koff = kbase + (k0 + 16) / 2;
            nah = *(const uint4*)(Ahi + (size_t)(m0 + lrow) * Khalf + koff + lcol);
            nal = *(const uint4*)(Alo + (size_t)(m0 + lrow) * Khalf + koff + lcol);
            nbh = *(const uint4*)(Bhi + (size_t)(n0 + lrow) * Khalf + koff + lcol);
            nbl = *(const uint4*)(Blo + (size_t)(n0 + lrow) * Khalf + koff + lcol);
        }

        unsigned ah[2][4], al[2][4];
#pragma unroll
        for (int mt = 0; mt < 2; mt++) {
            int mb = wm * 32 + mt * 16;
            ah[mt][0] = As_hi[cur][mb + g    ][t];
            ah[mt][1] = As_hi[cur][mb + g + 8][t];
            ah[mt][2] = As_hi[cur][mb + g    ][t + 4];
            ah[mt][3] = As_hi[cur][mb + g + 8][t + 4];
            al[mt][0] = As_lo[cur][mb + g    ][t];
            al[mt][1] = As_lo[cur][mb + g + 8][t];
            al[mt][2] = As_lo[cur][mb + g    ][t + 4];
            al[mt][3] = As_lo[cur][mb + g + 8][t + 4];
        }
#pragma unroll
        for (int nt = 0; nt < 8; nt++) {
            int nb = wn * 64 + nt * 8;
            unsigned bh0 = Bs_hi[cur][nb + g][t];
            unsigned bh1 = Bs_hi[cur][nb + g][t + 4];
            unsigned bl0 = Bs_lo[cur][nb + g][t];
            unsigned bl1 = Bs_lo[cur][nb + g][t + 4];
#pragma unroll
            for (int mt = 0; mt < 2; mt++) {
                mma16(acc[mt][nt], al[mt], bh0, bh1);
                mma16(acc[mt][nt], ah[mt], bl0, bl1);
                mma16(acc[mt][nt], ah[mt], bh0, bh1);
            }
        }

        if (hasNext) {
            int nxt = cur ^ 1;
            *(uint4*)&As_hi[nxt][lrow][lcol] = nah;
            *(uint4*)&As_lo[nxt][lrow][lcol] = nal;
            *(uint4*)&Bs_hi[nxt][lrow][lcol] = nbh;
            *(uint4*)&Bs_lo[nxt][lrow][lcol] = nbl;
        }
        cur ^= 1;
    }

    float* Cout = C + (size_t)kr * BB * NCAT;
#pragma unroll
    for (int mt = 0; mt < 2; mt++) {
        int r0 = m0 + wm * 32 + mt * 16 + g;
#pragma unroll
        for (int nt = 0; nt < 8; nt++) {
            int col = n0 + wn * 64 + nt * 8 + 2 * t;
            float bv0 = (kr == 0) ? bias[col] : 0.0f;
            float bv1 = (kr == 0) ? bias[col + 1] : 0.0f;
            float2 v;
            v.x = acc[mt][nt][0] + bv0; v.y = acc[mt][nt][1] + bv1;
            *(float2*)&Cout[(size_t)r0 * NCAT + col] = v;
            v.x = acc[mt][nt][2] + bv0; v.y = acc[mt][nt][3] + bv1;
            *(float2*)&Cout[(size_t)(r0 + 8) * NCAT + col] = v;
        }
    }
}

// ---------------------------------------------------------------------------
// Per-step fusion: block-per-row, 256 threads, reads BOTH Zh k-halves and
// sums at load sites (no extra live registers). Otherwise R11-identical.
// ---------------------------------------------------------------------------
__global__ void __launch_bounds__(256)
step_kernel(int t,
            const float* __restrict__ gum,
            const float* __restrict__ W2,
            const float* __restrict__ b2,
            const float* __restrict__ temp_ptr,
            const float* __restrict__ wpos,
            const float* __restrict__ F,
            const float* __restrict__ Zh0,
            const float* __restrict__ Zh1,
            unsigned* __restrict__ h_hi,
            unsigned* __restrict__ h_lo,
            float* __restrict__ out_pos,
            float* __restrict__ out_states,
            float* __restrict__ out_hfinal)
{
    const int b = blockIdx.x;
    const int tid = threadIdx.x;
    const int warp = tid >> 5, lane = tid & 31;
    const size_t bt = (size_t)b * TT + t;

    __shared__ float sh_hidden[HH1];
    __shared__ float sh_logits[PP];
    __shared__ float sh_pos;

    const float* Frow = F + bt * NCAT;
    const float* Zrow0 = Zh0 + (size_t)b * NCAT;
    const float* Zrow1 = Zh1 + (size_t)b * NCAT;

    const int j = tid;   // 0..255 == SS
    __nv_bfloat16 hold_hi = ((const __nv_bfloat16*)h_hi)[(size_t)b * SS + j];
    __nv_bfloat16 hold_lo = ((const __nv_bfloat16*)h_lo)[(size_t)b * SS + j];
    float f_r = Frow[HH1 + j];
    float f_z = Frow[HH1 + SS + j];
    float f_n = Frow[HH1 + 2 * SS + j];
    float z_r = Zrow0[HH1 + j]          + Zrow1[HH1 + j];
    float z_z = Zrow0[HH1 + SS + j]     + Zrow1[HH1 + SS + j];
    float z_n = Zrow0[HH1 + 2 * SS + j] + Zrow1[HH1 + 2 * SS + j];
    float wp_r = wpos[j];
    float wp_z = wpos[SS + j];
    float wp_n = wpos[2 * SS + j];

    float2 hf2, hz2;
    if (tid < 192) {
        hf2 = ((const float2*)Frow)[tid];
        float2 a = ((const float2*)Zrow0)[tid];
        float2 c = ((const float2*)Zrow1)[tid];
        hz2.x = a.x + c.x;
        hz2.y = a.y + c.y;
    }

    float gv = 0.0f, temp = 1.0f;
    if (warp == 0) {
        temp = *temp_ptr;
        if (lane < PP) gv = gum[bt * PP + lane];
    }

    if (tid < 192) {
        float2 r;
        r.x = fmaxf(hf2.x + hz2.x, 0.0f);
        r.y = fmaxf(hf2.y + hz2.y, 0.0f);
        ((float2*)sh_hidden)[tid] = r;
    }
    __syncthreads();

    {
        const float4* h4 = (const float4*)sh_hidden;
        const float4* W2a = (const float4*)(W2 + warp * HH1);
        float s = 0.0f;
#pragma unroll
        for (int i = 0; i < 3; i++) {
            float4 w = W2a[lane + 32 * i], hh = h4[lane + 32 * i];
            s = fmaf(w.x, hh.x, s); s = fmaf(w.y, hh.y, s);
            s = fmaf(w.z, hh.z, s); s = fmaf(w.w, hh.w, s);
        }
#pragma unroll
        for (int off = 16; off > 0; off >>= 1)
            s += __shfl_xor_sync(0xffffffffu, s, off);
        if (lane == 0) sh_logits[warp] = s + b2[warp];

        if (warp < 3) {
            const float4* W2b = (const float4*)(W2 + (warp + 8) * HH1);
            float s2 = 0.0f;
#pragma unroll
            for (int i = 0; i < 3; i++) {
                float4 w = W2b[lane + 32 * i], hh = h4[lane + 32 * i];
                s2 = fmaf(w.x, hh.x, s2); s2 = fmaf(w.y, hh.y, s2);
                s2 = fmaf(w.z, hh.z, s2); s2 = fmaf(w.w, hh.w, s2);
            }
#pragma unroll
            for (int off = 16; off > 0; off >>= 1)
                s2 += __shfl_xor_sync(0xffffffffu, s2, off);
            if (lane == 0) sh_logits[warp + 8] = s2 + b2[warp + 8];
        }
    }
    __syncthreads();

    if (warp == 0) {
        float val = -INFINITY;
        if (lane < PP) val = (sh_logits[lane] + gv) / temp;
        float m = val;
#pragma unroll
        for (int off = 16; off > 0; off >>= 1)
            m = fmaxf(m, __shfl_xor_sync(0xffffffffu, m, off));
        float e = (lane < PP) ? __expf(val - m) : 0.0f;
        float s = e;
        float w = (lane < PP) ? e * (float)lane : 0.0f;
#pragma unroll
        for (int off = 16; off > 0; off >>= 1) {
            s += __shfl_xor_sync(0xffffffffu, s, off);
            w += __shfl_xor_sync(0xffffffffu, w, off);
        }
        if (lane == 0) {
            float pos = w / s;
            sh_pos = pos;
            out_pos[bt] = pos;
        }
    }
    __syncthreads();
    const float pos = sh_pos;

    float hold = __bfloat162float(hold_hi) + __bfloat162float(hold_lo);
    float gi_r = f_r + pos * wp_r;
    float gi_z = f_z + pos * wp_z;
    float gi_n = f_n + pos * wp_n;

    float r = 1.0f / (1.0f + __expf(-(gi_r + z_r)));
    float z = 1.0f / (1.0f + __expf(-(gi_z + z_z)));
    float xn = gi_n + r * z_n;
    float n = 1.0f - 2.0f / (__expf(2.0f * xn) + 1.0f);
    float hnew = (1.0f - z) * n + z * hold;

    {
        __nv_bfloat16 bh = __float2bfloat16(hnew);
        ((__nv_bfloat16*)h_hi)[(size_t)b * SS + j] = bh;
        ((__nv_bfloat16*)h_lo)[(size_t)b * SS + j] =
            __float2bfloat16(hnew - __bfloat162float(bh));
    }
    out_states[bt * SS + j] = hnew;
    if (t == TT - 1) out_hfinal[(size_t)b * SS + j] = hnew;
}

// ---------------------------------------------------------------------------
extern "C" void kernel_launch(void* const* d_in, const int* in_sizes, int n_in,
                              void* d_out, int out_size)
{
    const float* price = (const float*)d_in[0];
    const float* u     = (const float*)d_in[1];
    const float* W1    = (const float*)d_in[2];
    const float* b1    = (const float*)d_in[3];
    const float* W2    = (const float*)d_in[4];
    const float* b2    = (const float*)d_in[5];
    const float* temp  = (const float*)d_in[6];
    const float* W_ih  = (const float*)d_in[7];
    const float* b_ih  = (const float*)d_in[8];
    const float* W_hh  = (const float*)d_in[9];
    const float* b_hh  = (const float*)d_in[10];
    const float* h0    = (const float*)d_in[11];

    float* scratch = nullptr;
    cudaGetSymbolAddress((void**)&scratch, g_scratch);
    float* F      = scratch + OFF_F;
    float* Zh0    = scratch + OFF_ZH0;
    float* Zh1    = scratch + OFF_ZH1;
    float* gum    = scratch + OFF_GUM;
    float* wpos   = scratch + OFF_WPOS;
    float* bf     = scratch + OFF_BF;
    float* bzh    = scratch + OFF_BZH;
    unsigned* Wfhi = (unsigned*)(scratch + OFF_WFHI);
    unsigned* Wflo = (unsigned*)(scratch + OFF_WFLO);
    unsigned* Whhi = (unsigned*)(scratch + OFF_WHHI);
    unsigned* Whlo = (unsigned*)(scratch + OFF_WHLO);
    unsigned* h_hi = (unsigned*)(scratch + OFF_HHI);
    unsigned* h_lo = (unsigned*)(scratch + OFF_HLO);

    float* out        = (float*)d_out;
    float* out_pos    = out;                                  // [B, T]
    float* out_states = out + (size_t)BB * TT;                // [B, T, S]
    float* out_hf     = out_states + (size_t)BB * TT * SS;    // [B, S]

    // 1. pack + gumbel precompute
    pack_kernel<<<(BB * SS + 255) / 256, 256>>>(W1, b1, W_ih, b_ih, W_hh, b_hh,
                                                h0, Wfhi, Wflo, Whhi, Whlo,
                                                bf, bzh, h_hi, h_lo, wpos);
    gumbel_kernel<<<(BB * TT * PP + 255) / 256, 256>>>(u, gum);

    // 2. big parallel GEMM: F[B*T, NCAT] = feats @ Wf^T + bf
    {
        dim3 grid(NCAT / 128, (BB * TT) / 128);   // (9, 1024)
        gemm_f<<<grid, 256>>>(price, Wfhi, Wflo, bf, F);
    }

    // 3. sequential recurrence: split-K Zh (288 blocks, 2 CTA/SM) + step
    for (int t = 0; t < TT; t++) {
        dim3 grid(NCAT / 128, BB / 128, 2);       // (9, 16, 2) = 288 blocks
        gemm_zh<<<grid, 256>>>(h_hi, h_lo, Whhi, Whlo, bzh, Zh0);
        step_kernel<<<BB, 256>>>(t, gum, W2, b2, temp, wpos,
                                 F, Zh0, Zh1, h_hi, h_lo,
                                 out_pos, out_states, out_hf);
    }
}

// round 15
// speedup vs baseline: 1.1244x; 1.0294x over previous
#include <cuda_runtime.h>
#include <cuda_bf16.h>
#include <math.h>
#include <stdint.h>

// Problem dims
#define BB 2048
#define TT 64
#define DD 512
#define SS 256
#define PP 11
#define HH1 384
#define NCAT 1152   // HH1 + 3*SS

// Scratch layout (float units) in one __device__ array
#define OFF_F    ((size_t)0)                          // [B*T, NCAT] (b-major)
#define SZ_F     ((size_t)BB * TT * NCAT)
#define OFF_ZH   (OFF_F + SZ_F)                       // [B, NCAT]
#define SZ_ZH    ((size_t)BB * NCAT)
#define OFF_GUM  (OFF_ZH + SZ_ZH)                     // [B*T*P] gumbel noise
#define SZ_GUM   ((size_t)BB * TT * PP)
#define OFF_WPOS (OFF_GUM + SZ_GUM)                   // [3*S]
#define SZ_WPOS  ((size_t)768)
#define OFF_BF   (OFF_WPOS + SZ_WPOS)                 // [NCAT] bias for F
#define SZ_BF    ((size_t)1280)
#define OFF_BZH  (OFF_BF + SZ_BF)                     // [NCAT] bias for Zh
#define SZ_BZH   ((size_t)1280)
#define OFF_WFHI (OFF_BZH + SZ_BZH)                   // u32 [NCAT][DD/2]
#define SZ_WFHI  ((size_t)NCAT * DD / 2)
#define OFF_WFLO (OFF_WFHI + SZ_WFHI)
#define OFF_WHHI (OFF_WFLO + SZ_WFHI)                 // u32 [NCAT][SS/2]
#define SZ_WHHI  ((size_t)NCAT * SS / 2)
#define OFF_WHLO (OFF_WHHI + SZ_WHHI)
#define OFF_HHI  (OFF_WHLO + SZ_WHHI)                 // u32 [B][SS/2] bf16 pairs
#define SZ_HHI   ((size_t)BB * SS / 2)
#define OFF_HLO  (OFF_HHI + SZ_HHI)
#define SCRATCH_TOTAL (OFF_HLO + SZ_HHI)

__device__ float g_scratch[SCRATCH_TOTAL];

// ---------------------------------------------------------------------------
__device__ __forceinline__ void split_pack(float x, float y,
                                           unsigned& hi, unsigned& lo) {
    __nv_bfloat162 h2 = __float22bfloat162_rn(make_float2(x, y));
    float rx = x - __bfloat162float(h2.x);
    float ry = y - __bfloat162float(h2.y);
    __nv_bfloat162 l2 = __float22bfloat162_rn(make_float2(rx, ry));
    hi = reinterpret_cast<unsigned&>(h2);
    lo = reinterpret_cast<unsigned&>(l2);
}

// ---------------------------------------------------------------------------
// Pack kernel: pre-split fused weights to bf16 hi/lo, biases, wpos, h init
// ---------------------------------------------------------------------------
__global__ void pack_kernel(const float* __restrict__ W1,
                            const float* __restrict__ b1,
                            const float* __restrict__ W_ih,
                            const float* __restrict__ b_ih,
                            const float* __restrict__ W_hh,
                            const float* __restrict__ b_hh,
                            const float* __restrict__ h0,
                            unsigned* __restrict__ Wfhi,
                            unsigned* __restrict__ Wflo,
                            unsigned* __restrict__ Whhi,
                            unsigned* __restrict__ Whlo,
                            float* __restrict__ bf,
                            float* __restrict__ bzh,
                            unsigned* __restrict__ h_hi,
                            unsigned* __restrict__ h_lo,
                            float* __restrict__ wpos)
{
    int i = blockIdx.x * blockDim.x + threadIdx.x;
    if (i < NCAT * DD / 2) {
        int n = i / (DD / 2), kp = i % (DD / 2);
        int k0 = 2 * kp;
        float v0, v1;
        if (n < HH1) {
            v0 = W1[n * (DD + SS) + k0];
            v1 = W1[n * (DD + SS) + k0 + 1];
        } else {
            v0 = W_ih[(size_t)(n - HH1) * (DD + 1) + k0];
            v1 = W_ih[(size_t)(n - HH1) * (DD + 1) + k0 + 1];
        }
        unsigned hi, lo;
        split_pack(v0, v1, hi, lo);
        Wfhi[i] = hi; Wflo[i] = lo;
    }
    if (i < NCAT * SS / 2) {
        int n = i / (SS / 2), kp = i % (SS / 2);
        int k0 = 2 * kp;
        float v0, v1;
        if (n < HH1) {
            v0 = W1[n * (DD + SS) + DD + k0];
            v1 = W1[n * (DD + SS) + DD + k0 + 1];
        } else {
            v0 = W_hh[(n - HH1) * SS + k0];
            v1 = W_hh[(n - HH1) * SS + k0 + 1];
        }
        unsigned hi, lo;
        split_pack(v0, v1, hi, lo);
        Whhi[i] = hi; Whlo[i] = lo;
    }
    if (i < NCAT) {
        bf[i]  = (i < HH1) ? b1[i] : b_ih[i - HH1];
        bzh[i] = (i < HH1) ? 0.0f : b_hh[i - HH1];
    }
    if (i < BB * SS) {
        float v = h0[i % SS];
        __nv_bfloat16 bh = __float2bfloat16(v);
        ((__nv_bfloat16*)h_hi)[i] = bh;
        ((__nv_bfloat16*)h_lo)[i] = __float2bfloat16(v - __bfloat162float(bh));
    }
    if (i < 3 * SS) wpos[i] = W_ih[(size_t)i * (DD + 1) + DD];
}

// ---------------------------------------------------------------------------
// Gumbel precompute
// ---------------------------------------------------------------------------
__global__ void gumbel_kernel(const float* __restrict__ u,
                              float* __restrict__ gum)
{
    int i = blockIdx.x * blockDim.x + threadIdx.x;
    if (i < BB * TT * PP) {
        float uu = u[i];
        gum[i] = -logf(-logf(uu + 1e-20f) + 1e-20f);
    }
}

// ---------------------------------------------------------------------------
__device__ __forceinline__ void mma16(float* c, const unsigned* a,
                                      unsigned b0, unsigned b1) {
    asm volatile(
        "mma.sync.aligned.m16n8k16.row.col.f32.bf16.bf16.f32 "
        "{%0,%1,%2,%3}, {%4,%5,%6,%7}, {%8,%9}, {%0,%1,%2,%3};\n"
        : "+f"(c[0]), "+f"(c[1]), "+f"(c[2]), "+f"(c[3])
        : "r"(a[0]), "r"(a[1]), "r"(a[2]), "r"(a[3]), "r"(b0), "r"(b1));
}

#define KW 12   // padded u32 k-stride (8 used) -> conflict-free fragment loads

// ---------------------------------------------------------------------------
// Big F GEMM (R11, measured-best): symmetric 3-pass, double-buffered.
// BM=BN=128, BK=16, 8 warps (4m x 2n).
// ---------------------------------------------------------------------------
__global__ void __launch_bounds__(256, 2)
gemm_f(const float* __restrict__ A,
       const unsigned* __restrict__ Bhi,
       const unsigned* __restrict__ Blo,
       const float* __restrict__ bias,
       float* __restrict__ C)
{
    const int K = DD, N = NCAT;
    __shared__ unsigned As_hi[2][128][KW];
    __shared__ unsigned As_lo[2][128][KW];
    __shared__ unsigned Bs_hi[2][128][KW];
    __shared__ unsigned Bs_lo[2][128][KW];

    const int tid  = threadIdx.x;
    const int warp = tid >> 5, lane = tid & 31;
    const int g = lane >> 2, t = lane & 3;
    const int wm = warp >> 1, wn = warp & 1;   // 4 x 2 warp grid

    const int n0 = blockIdx.x * 128;
    const int m0 = blockIdx.y * 128;

    const int lrowA = tid >> 2;
    const int lcolA = (tid & 3) * 4;
    const int lc2   = (tid & 3) * 2;
    const int lrowB = tid >> 1;
    const int lcolB = (tid & 1) * 4;
    const int Khalf = K >> 1;

    float acc[2][8][4];
#pragma unroll
    for (int mt = 0; mt < 2; mt++)
#pragma unroll
        for (int nt = 0; nt < 8; nt++)
#pragma unroll
            for (int r = 0; r < 4; r++) acc[mt][nt][r] = 0.0f;

    {
#pragma unroll
        for (int i = 0; i < 2; i++) {
            float4 v = *(const float4*)(A + (size_t)(m0 + lrowA + i * 64) * K + lcolA);
            int row = lrowA + i * 64;
            unsigned h0, l0, h1, l1;
            split_pack(v.x, v.y, h0, l0);
            split_pack(v.z, v.w, h1, l1);
            As_hi[0][row][lc2] = h0; As_hi[0][row][lc2 + 1] = h1;
            As_lo[0][row][lc2] = l0; As_lo[0][row][lc2 + 1] = l1;
        }
        *(uint4*)&Bs_hi[0][lrowB][lcolB] =
            *(const uint4*)(Bhi + (size_t)(n0 + lrowB) * Khalf + lcolB);
        *(uint4*)&Bs_lo[0][lrowB][lcolB] =
            *(const uint4*)(Blo + (size_t)(n0 + lrowB) * Khalf + lcolB);
    }

    int cur = 0;
    for (int k0 = 0; k0 < K; k0 += 16) {
        __syncthreads();
        const bool hasNext = (k0 + 16 < K);

        float4 na[2];
        uint4 nbh, nbl;
        if (hasNext) {
            int koff = k0 + 16;
#pragma unroll
            for (int i = 0; i < 2; i++)
                na[i] = *(const float4*)(A + (size_t)(m0 + lrowA + i * 64) * K + koff + lcolA);
            nbh = *(const uint4*)(Bhi + (size_t)(n0 + lrowB) * Khalf + koff / 2 + lcolB);
            nbl = *(const uint4*)(Blo + (size_t)(n0 + lrowB) * Khalf + koff / 2 + lcolB);
        }

        unsigned ah[2][4], al[2][4];
#pragma unroll
        for (int mt = 0; mt < 2; mt++) {
            int mb = wm * 32 + mt * 16;
            ah[mt][0] = As_hi[cur][mb + g    ][t];
            ah[mt][1] = As_hi[cur][mb + g + 8][t];
            ah[mt][2] = As_hi[cur][mb + g    ][t + 4];
            ah[mt][3] = As_hi[cur][mb + g + 8][t + 4];
            al[mt][0] = As_lo[cur][mb + g    ][t];
            al[mt][1] = As_lo[cur][mb + g + 8][t];
            al[mt][2] = As_lo[cur][mb + g    ][t + 4];
            al[mt][3] = As_lo[cur][mb + g + 8][t + 4];
        }
#pragma unroll
        for (int nt = 0; nt < 8; nt++) {
            int nb = wn * 64 + nt * 8;
            unsigned bh0 = Bs_hi[cur][nb + g][t];
            unsigned bh1 = Bs_hi[cur][nb + g][t + 4];
            unsigned bl0 = Bs_lo[cur][nb + g][t];
            unsigned bl1 = Bs_lo[cur][nb + g][t + 4];
#pragma unroll
            for (int mt = 0; mt < 2; mt++) {
                mma16(acc[mt][nt], al[mt], bh0, bh1);
                mma16(acc[mt][nt], ah[mt], bl0, bl1);
                mma16(acc[mt][nt], ah[mt], bh0, bh1);
            }
        }

        if (hasNext) {
            int nxt = cur ^ 1;
#pragma unroll
            for (int i = 0; i < 2; i++) {
                int row = lrowA + i * 64;
                unsigned h0, l0, h1, l1;
                split_pack(na[i].x, na[i].y, h0, l0);
                split_pack(na[i].z, na[i].w, h1, l1);
                As_hi[nxt][row][lc2] = h0; As_hi[nxt][row][lc2 + 1] = h1;
                As_lo[nxt][row][lc2] = l0; As_lo[nxt][row][lc2 + 1] = l1;
            }
            *(uint4*)&Bs_hi[nxt][lrowB][lcolB] = nbh;
            *(uint4*)&Bs_lo[nxt][lrowB][lcolB] = nbl;
        }
        cur ^= 1;
    }

#pragma unroll
    for (int mt = 0; mt < 2; mt++) {
        int r0 = m0 + wm * 32 + mt * 16 + g;
#pragma unroll
        for (int nt = 0; nt < 8; nt++) {
            int col = n0 + wn * 64 + nt * 8 + 2 * t;
            float bv0 = bias[col], bv1 = bias[col + 1];
            float2 v;
            v.x = acc[mt][nt][0] + bv0; v.y = acc[mt][nt][1] + bv1;
            *(float2*)&C[(size_t)r0 * N + col] = v;
            v.x = acc[mt][nt][2] + bv0; v.y = acc[mt][nt][3] + bv1;
            *(float2*)&C[(size_t)(r0 + 8) * N + col] = v;
        }
    }
}

// ---------------------------------------------------------------------------
// Recurrent Zh GEMM: cp.async pipelined, BK=32, tile 128x128, grid (9,16).
// Operands pre-split bf16 hi/lo. 8 barriers for K=256 (vs 16 before); loads
// flow global->smem asynchronously with no register staging.
// Dynamic smem: 4 arrays x 2 stages x 128 rows x 20 u32 = 81920 B.
// ---------------------------------------------------------------------------
#define ZKW 20                         // u32 row stride (16 data + 4 pad)
#define ZARR ((size_t)2 * 128 * ZKW)   // u32 per operand array (both stages)
#define ZSTG ((size_t)128 * ZKW)       // u32 per stage

__device__ __forceinline__ void cp16(unsigned dst_smem, const void* src) {
    asm volatile("cp.async.ca.shared.global [%0], [%1], 16;"
                 :: "r"(dst_smem), "l"(src));
}
__device__ __forceinline__ unsigned smem_addr_u32(const void* p) {
    unsigned a;
    asm("{ .reg .u64 tmp; cvta.to.shared.u64 tmp, %1; cvt.u32.u64 %0, tmp; }"
        : "=r"(a) : "l"(p));
    return a;
}

__global__ void __launch_bounds__(256, 1)
gemm_zh(const unsigned* __restrict__ Ahi,
        const unsigned* __restrict__ Alo,
        const unsigned* __restrict__ Bhi,
        const unsigned* __restrict__ Blo,
        const float* __restrict__ bias,
        float* __restrict__ C)
{
    extern __shared__ unsigned zs[];
    unsigned* sAhi = zs;
    unsigned* sAlo = zs + ZARR;
    unsigned* sBhi = zs + 2 * ZARR;
    unsigned* sBlo = zs + 3 * ZARR;
    const unsigned smb = smem_addr_u32(zs);

    const int tid  = threadIdx.x;
    const int warp = tid >> 5, lane = tid & 31;
    const int g = lane >> 2, t = lane & 3;
    const int wm = warp >> 1, wn = warp & 1;   // 4 x 2 warp grid

    const int n0 = blockIdx.x * 128;
    const int m0 = blockIdx.y * 128;
    const int Khalf = SS / 2;            // 128 u32 per operand row

    const int lrow = tid >> 1;           // 0..127
    const int lc   = (tid & 1) * 8;      // u32 col within the 16-u32 stage

    const size_t srcA = (size_t)(m0 + lrow) * Khalf;
    const size_t srcB = (size_t)(n0 + lrow) * Khalf;
    const unsigned dstRow = (unsigned)(lrow * ZKW + lc);

    float acc[2][8][4];
#pragma unroll
    for (int mt = 0; mt < 2; mt++)
#pragma unroll
        for (int nt = 0; nt < 8; nt++)
#pragma unroll
            for (int r = 0; r < 4; r++) acc[mt][nt][r] = 0.0f;

    // stage loader: stage 'buf' from u32 k-offset 'ko'
    auto load_stage = [&](int buf, int ko) {
        unsigned base = smb + (unsigned)(buf * ZSTG + dstRow) * 4u;
        cp16(base + (unsigned)(0 * ZARR * 4), Ahi + srcA + ko + lc);
        cp16(base + (unsigned)(0 * ZARR * 4) + 16, Ahi + srcA + ko + lc + 4);
        cp16(base + (unsigned)(1 * ZARR * 4), Alo + srcA + ko + lc);
        cp16(base + (unsigned)(1 * ZARR * 4) + 16, Alo + srcA + ko + lc + 4);
        cp16(base + (unsigned)(2 * ZARR * 4), Bhi + srcB + ko + lc);
        cp16(base + (unsigned)(2 * ZARR * 4) + 16, Bhi + srcB + ko + lc + 4);
        cp16(base + (unsigned)(3 * ZARR * 4), Blo + srcB + ko + lc);
        cp16(base + (unsigned)(3 * ZARR * 4) + 16, Blo + srcB + ko + lc + 4);
        asm volatile("cp.async.commit_group;" ::: "memory");
    };

    load_stage(0, 0);

    int cur = 0;
    for (int it = 0; it < 8; it++) {           // 8 x BK=32
        asm volatile("cp.async.wait_group 0;" ::: "memory");
        __syncthreads();
        if (it + 1 < 8) load_stage(cur ^ 1, (it + 1) * 16);

        const unsigned* bA_hi = sAhi + cur * ZSTG;
        const unsigned* bA_lo = sAlo + cur * ZSTG;
        const unsigned* bB_hi = sBhi + cur * ZSTG;
        const unsigned* bB_lo = sBlo + cur * ZSTG;

#pragma unroll
        for (int kk = 0; kk < 16; kk += 8) {   // two k16 slabs
            unsigned ah[2][4], al[2][4];
#pragma unroll
            for (int mt = 0; mt < 2; mt++) {
                int mb = wm * 32 + mt * 16;
                ah[mt][0] = bA_hi[(mb + g    ) * ZKW + kk + t];
                ah[mt][1] = bA_hi[(mb + g + 8) * ZKW + kk + t];
                ah[mt][2] = bA_hi[(mb + g    ) * ZKW + kk + t + 4];
                ah[mt][3] = bA_hi[(mb + g + 8) * ZKW + kk + t + 4];
                al[mt][0] = bA_lo[(mb + g    ) * ZKW + kk + t];
                al[mt][1] = bA_lo[(mb + g + 8) * ZKW + kk + t];
                al[mt][2] = bA_lo[(mb + g    ) * ZKW + kk + t + 4];
                al[mt][3] = bA_lo[(mb + g + 8) * ZKW + kk + t + 4];
            }
#pragma unroll
            for (int nt = 0; nt < 8; nt++) {
                int nb = wn * 64 + nt * 8;
                unsigned bh0 = bB_hi[(nb + g) * ZKW + kk + t];
                unsigned bh1 = bB_hi[(nb + g) * ZKW + kk + t + 4];
                unsigned bl0 = bB_lo[(nb + g) * ZKW + kk + t];
                unsigned bl1 = bB_lo[(nb + g) * ZKW + kk + t + 4];
#pragma unroll
                for (int mt = 0; mt < 2; mt++) {
                    mma16(acc[mt][nt], al[mt], bh0, bh1);
                    mma16(acc[mt][nt], ah[mt], bl0, bl1);
                    mma16(acc[mt][nt], ah[mt], bh0, bh1);
                }
            }
        }
        __syncthreads();   // all reads of buffer cur done before next overwrite
        cur ^= 1;
    }

#pragma unroll
    for (int mt = 0; mt < 2; mt++) {
        int r0 = m0 + wm * 32 + mt * 16 + g;
#pragma unroll
        for (int nt = 0; nt < 8; nt++) {
            int col = n0 + wn * 64 + nt * 8 + 2 * t;
            float bv0 = bias[col], bv1 = bias[col + 1];
            float2 v;
            v.x = acc[mt][nt][0] + bv0; v.y = acc[mt][nt][1] + bv1;
            *(float2*)&C[(size_t)r0 * NCAT + col] = v;
            v.x = acc[mt][nt][2] + bv0; v.y = acc[mt][nt][3] + bv1;
            *(float2*)&C[(size_t)(r0 + 8) * NCAT + col] = v;
        }
    }
}
#define ZH_SMEM_BYTES ((int)(4 * ZARR * 4))   // 81920

// ---------------------------------------------------------------------------
// Per-step fusion (R11, measured-best): block-per-row, 256 threads,
// slim registers, precomputed gumbel, bf16 hold, MUFU fast-exp gates.
// ---------------------------------------------------------------------------
__global__ void __launch_bounds__(256)
step_kernel(int t,
            const float* __restrict__ gum,
            const float* __restrict__ W2,
            const float* __restrict__ b2,
            const float* __restrict__ temp_ptr,
            const float* __restrict__ wpos,
            const float* __restrict__ F,
            const float* __restrict__ Zh,
            unsigned* __restrict__ h_hi,
            unsigned* __restrict__ h_lo,
            float* __restrict__ out_pos,
            float* __restrict__ out_states,
            float* __restrict__ out_hfinal)
{
    const int b = blockIdx.x;
    const int tid = threadIdx.x;
    const int warp = tid >> 5, lane = tid & 31;
    const size_t bt = (size_t)b * TT + t;

    __shared__ float sh_hidden[HH1];
    __shared__ float sh_logits[PP];
    __shared__ float sh_pos;

    const float* Frow = F + bt * NCAT;
    const float* Zrow = Zh + (size_t)b * NCAT;

    const int j = tid;   // 0..255 == SS
    __nv_bfloat16 hold_hi = ((const __nv_bfloat16*)h_hi)[(size_t)b * SS + j];
    __nv_bfloat16 hold_lo = ((const __nv_bfloat16*)h_lo)[(size_t)b * SS + j];
    float f_r = Frow[HH1 + j];
    float f_z = Frow[HH1 + SS + j];
    float f_n = Frow[HH1 + 2 * SS + j];
    float z_r = Zrow[HH1 + j];
    float z_z = Zrow[HH1 + SS + j];
    float z_n = Zrow[HH1 + 2 * SS + j];
    float wp_r = wpos[j];
    float wp_z = wpos[SS + j];
    float wp_n = wpos[2 * SS + j];

    float2 hf2, hz2;
    if (tid < 192) {
        hf2 = ((const float2*)Frow)[tid];
        hz2 = ((const float2*)Zrow)[tid];
    }

    float gv = 0.0f, temp = 1.0f;
    if (warp == 0) {
        temp = *temp_ptr;
        if (lane < PP) gv = gum[bt * PP + lane];
    }

    if (tid < 192) {
        float2 r;
        r.x = fmaxf(hf2.x + hz2.x, 0.0f);
        r.y = fmaxf(hf2.y + hz2.y, 0.0f);
        ((float2*)sh_hidden)[tid] = r;
    }
    __syncthreads();

    {
        const float4* h4 = (const float4*)sh_hidden;
        const float4* W2a = (const float4*)(W2 + warp * HH1);
        float s = 0.0f;
#pragma unroll
        for (int i = 0; i < 3; i++) {
            float4 w = W2a[lane + 32 * i], hh = h4[lane + 32 * i];
            s = fmaf(w.x, hh.x, s); s = fmaf(w.y, hh.y, s);
            s = fmaf(w.z, hh.z, s); s = fmaf(w.w, hh.w, s);
        }
#pragma unroll
        for (int off = 16; off > 0; off >>= 1)
            s += __shfl_xor_sync(0xffffffffu, s, off);
        if (lane == 0) sh_logits[warp] = s + b2[warp];

        if (warp < 3) {
            const float4* W2b = (const float4*)(W2 + (warp + 8) * HH1);
            float s2 = 0.0f;
#pragma unroll
            for (int i = 0; i < 3; i++) {
                float4 w = W2b[lane + 32 * i], hh = h4[lane + 32 * i];
                s2 = fmaf(w.x, hh.x, s2); s2 = fmaf(w.y, hh.y, s2);
                s2 = fmaf(w.z, hh.z, s2); s2 = fmaf(w.w, hh.w, s2);
            }
#pragma unroll
            for (int off = 16; off > 0; off >>= 1)
                s2 += __shfl_xor_sync(0xffffffffu, s2, off);
            if (lane == 0) sh_logits[warp + 8] = s2 + b2[warp + 8];
        }
    }
    __syncthreads();

    if (warp == 0) {
        float val = -INFINITY;
        if (lane < PP) val = (sh_logits[lane] + gv) / temp;
        float m = val;
#pragma unroll
        for (int off = 16; off > 0; off >>= 1)
            m = fmaxf(m, __shfl_xor_sync(0xffffffffu, m, off));
        float e = (lane < PP) ? __expf(val - m) : 0.0f;
        float s = e;
        float w = (lane < PP) ? e * (float)lane : 0.0f;
#pragma unroll
        for (int off = 16; off > 0; off >>= 1) {
            s += __shfl_xor_sync(0xffffffffu, s, off);
            w += __shfl_xor_sync(0xffffffffu, w, off);
        }
        if (lane == 0) {
            float pos = w / s;
            sh_pos = pos;
            out_pos[bt] = pos;
        }
    }
    __syncthreads();
    const float pos = sh_pos;

    float hold = __bfloat162float(hold_hi) + __bfloat162float(hold_lo);
    float gi_r = f_r + pos * wp_r;
    float gi_z = f_z + pos * wp_z;
    float gi_n = f_n + pos * wp_n;

    float r = 1.0f / (1.0f + __expf(-(gi_r + z_r)));
    float z = 1.0f / (1.0f + __expf(-(gi_z + z_z)));
    float xn = gi_n + r * z_n;
    float n = 1.0f - 2.0f / (__expf(2.0f * xn) + 1.0f);
    float hnew = (1.0f - z) * n + z * hold;

    {
        __nv_bfloat16 bh = __float2bfloat16(hnew);
        ((__nv_bfloat16*)h_hi)[(size_t)b * SS + j] = bh;
        ((__nv_bfloat16*)h_lo)[(size_t)b * SS + j] =
            __float2bfloat16(hnew - __bfloat162float(bh));
    }
    out_states[bt * SS + j] = hnew;
    if (t == TT - 1) out_hfinal[(size_t)b * SS + j] = hnew;
}

// ---------------------------------------------------------------------------
extern "C" void kernel_launch(void* const* d_in, const int* in_sizes, int n_in,
                              void* d_out, int out_size)
{
    const float* price = (const float*)d_in[0];
    const float* u     = (const float*)d_in[1];
    const float* W1    = (const float*)d_in[2];
    const float* b1    = (const float*)d_in[3];
    const float* W2    = (const float*)d_in[4];
    const float* b2    = (const float*)d_in[5];
    const float* temp  = (const float*)d_in[6];
    const float* W_ih  = (const float*)d_in[7];
    const float* b_ih  = (const float*)d_in[8];
    const float* W_hh  = (const float*)d_in[9];
    const float* b_hh  = (const float*)d_in[10];
    const float* h0    = (const float*)d_in[11];

    float* scratch = nullptr;
    cudaGetSymbolAddress((void**)&scratch, g_scratch);
    float* F      = scratch + OFF_F;
    float* Zh     = scratch + OFF_ZH;
    float* gum    = scratch + OFF_GUM;
    float* wpos   = scratch + OFF_WPOS;
    float* bf     = scratch + OFF_BF;
    float* bzh    = scratch + OFF_BZH;
    unsigned* Wfhi = (unsigned*)(scratch + OFF_WFHI);
    unsigned* Wflo = (unsigned*)(scratch + OFF_WFLO);
    unsigned* Whhi = (unsigned*)(scratch + OFF_WHHI);
    unsigned* Whlo = (unsigned*)(scratch + OFF_WHLO);
    unsigned* h_hi = (unsigned*)(scratch + OFF_HHI);
    unsigned* h_lo = (unsigned*)(scratch + OFF_HLO);

    float* out        = (float*)d_out;
    float* out_pos    = out;                                  // [B, T]
    float* out_states = out + (size_t)BB * TT;                // [B, T, S]
    float* out_hf     = out_states + (size_t)BB * TT * SS;    // [B, S]

    cudaFuncSetAttribute(gemm_zh,
                         cudaFuncAttributeMaxDynamicSharedMemorySize,
                         ZH_SMEM_BYTES);

    // 1. pack + gumbel precompute
    pack_kernel<<<(BB * SS + 255) / 256, 256>>>(W1, b1, W_ih, b_ih, W_hh, b_hh,
                                                h0, Wfhi, Wflo, Whhi, Whlo,
                                                bf, bzh, h_hi, h_lo, wpos);
    gumbel_kernel<<<(BB * TT * PP + 255) / 256, 256>>>(u, gum);

    // 2. big parallel GEMM: F[B*T, NCAT] = feats @ Wf^T + bf
    {
        dim3 grid(NCAT / 128, (BB * TT) / 128);   // (9, 1024)
        gemm_f<<<grid, 256>>>(price, Wfhi, Wflo, bf, F);
    }

    // 3. sequential recurrence: cp.async BK=32 Zh + step
    for (int t = 0; t < TT; t++) {
        dim3 grid(NCAT / 128, BB / 128);          // (9, 16) = 144 blocks
        gemm_zh<<<grid, 256, ZH_SMEM_BYTES>>>(h_hi, h_lo, Whhi, Whlo, bzh, Zh);
        step_kernel<<<BB, 256>>>(t, gum, W2, b2, temp, wpos,
                                 F, Zh, h_hi, h_lo,
                                 out_pos, out_states, out_hf);
    }
}

// round 16
// speedup vs baseline: 1.1977x; 1.0652x over previous
#include <cuda_runtime.h>
#include <cuda_bf16.h>
#include <math.h>
#include <stdint.h>

// Problem dims
#define BB 2048
#define TT 64
#define DD 512
#define SS 256
#define PP 11
#define HH1 384
#define NCAT 1152   // HH1 + 3*SS

// Scratch layout (float units) in one __device__ array
#define OFF_F    ((size_t)0)                          // [B*T, NCAT] (b-major)
#define SZ_F     ((size_t)BB * TT * NCAT)
#define OFF_ZH   (OFF_F + SZ_F)                       // [B, NCAT]
#define SZ_ZH    ((size_t)BB * NCAT)
#define OFF_GUM  (OFF_ZH + SZ_ZH)                     // [B*T*P] gumbel noise
#define SZ_GUM   ((size_t)BB * TT * PP)
#define OFF_WPOS (OFF_GUM + SZ_GUM)                   // [3*S]
#define SZ_WPOS  ((size_t)768)
#define OFF_BF   (OFF_WPOS + SZ_WPOS)                 // [NCAT] bias for F
#define SZ_BF    ((size_t)1280)
#define OFF_BZH  (OFF_BF + SZ_BF)                     // [NCAT] bias for Zh
#define SZ_BZH   ((size_t)1280)
#define OFF_WFHI (OFF_BZH + SZ_BZH)                   // u32 [NCAT][DD/2]
#define SZ_WFHI  ((size_t)NCAT * DD / 2)
#define OFF_WFLO (OFF_WFHI + SZ_WFHI)
#define OFF_WHHI (OFF_WFLO + SZ_WFHI)                 // u32 [NCAT][SS/2]
#define SZ_WHHI  ((size_t)NCAT * SS / 2)
#define OFF_WHLO (OFF_WHHI + SZ_WHHI)
#define OFF_HHI  (OFF_WHLO + SZ_WHHI)                 // u32 [B][SS/2] bf16 pairs
#define SZ_HHI   ((size_t)BB * SS / 2)
#define OFF_HLO  (OFF_HHI + SZ_HHI)
#define SCRATCH_TOTAL (OFF_HLO + SZ_HHI)

__device__ float g_scratch[SCRATCH_TOTAL];

// ---------------------------------------------------------------------------
__device__ __forceinline__ void split_pack(float x, float y,
                                           unsigned& hi, unsigned& lo) {
    __nv_bfloat162 h2 = __float22bfloat162_rn(make_float2(x, y));
    float rx = x - __bfloat162float(h2.x);
    float ry = y - __bfloat162float(h2.y);
    __nv_bfloat162 l2 = __float22bfloat162_rn(make_float2(rx, ry));
    hi = reinterpret_cast<unsigned&>(h2);
    lo = reinterpret_cast<unsigned&>(l2);
}
__device__ __forceinline__ unsigned pack_hi_only(float x, float y) {
    __nv_bfloat162 h2 = __float22bfloat162_rn(make_float2(x, y));
    return reinterpret_cast<unsigned&>(h2);
}

// ---------------------------------------------------------------------------
// Pack kernel: pre-split fused weights to bf16 hi/lo, biases, wpos, h init
// ---------------------------------------------------------------------------
__global__ void pack_kernel(const float* __restrict__ W1,
                            const float* __restrict__ b1,
                            const float* __restrict__ W_ih,
                            const float* __restrict__ b_ih,
                            const float* __restrict__ W_hh,
                            const float* __restrict__ b_hh,
                            const float* __restrict__ h0,
                            unsigned* __restrict__ Wfhi,
                            unsigned* __restrict__ Wflo,
                            unsigned* __restrict__ Whhi,
                            unsigned* __restrict__ Whlo,
                            float* __restrict__ bf,
                            float* __restrict__ bzh,
                            unsigned* __restrict__ h_hi,
                            unsigned* __restrict__ h_lo,
                            float* __restrict__ wpos)
{
    int i = blockIdx.x * blockDim.x + threadIdx.x;
    if (i < NCAT * DD / 2) {
        int n = i / (DD / 2), kp = i % (DD / 2);
        int k0 = 2 * kp;
        float v0, v1;
        if (n < HH1) {
            v0 = W1[n * (DD + SS) + k0];
            v1 = W1[n * (DD + SS) + k0 + 1];
        } else {
            v0 = W_ih[(size_t)(n - HH1) * (DD + 1) + k0];
            v1 = W_ih[(size_t)(n - HH1) * (DD + 1) + k0 + 1];
        }
        unsigned hi, lo;
        split_pack(v0, v1, hi, lo);
        Wfhi[i] = hi; Wflo[i] = lo;
    }
    if (i < NCAT * SS / 2) {
        int n = i / (SS / 2), kp = i % (SS / 2);
        int k0 = 2 * kp;
        float v0, v1;
        if (n < HH1) {
            v0 = W1[n * (DD + SS) + DD + k0];
            v1 = W1[n * (DD + SS) + DD + k0 + 1];
        } else {
            v0 = W_hh[(n - HH1) * SS + k0];
            v1 = W_hh[(n - HH1) * SS + k0 + 1];
        }
        unsigned hi, lo;
        split_pack(v0, v1, hi, lo);
        Whhi[i] = hi; Whlo[i] = lo;
    }
    if (i < NCAT) {
        bf[i]  = (i < HH1) ? b1[i] : b_ih[i - HH1];
        bzh[i] = (i < HH1) ? 0.0f : b_hh[i - HH1];
    }
    if (i < BB * SS) {
        float v = h0[i % SS];
        __nv_bfloat16 bh = __float2bfloat16(v);
        ((__nv_bfloat16*)h_hi)[i] = bh;
        ((__nv_bfloat16*)h_lo)[i] = __float2bfloat16(v - __bfloat162float(bh));
    }
    if (i < 3 * SS) wpos[i] = W_ih[(size_t)i * (DD + 1) + DD];
}

// ---------------------------------------------------------------------------
// Gumbel precompute
// ---------------------------------------------------------------------------
__global__ void gumbel_kernel(const float* __restrict__ u,
                              float* __restrict__ gum)
{
    int i = blockIdx.x * blockDim.x + threadIdx.x;
    if (i < BB * TT * PP) {
        float uu = u[i];
        gum[i] = -logf(-logf(uu + 1e-20f) + 1e-20f);
    }
}

// ---------------------------------------------------------------------------
__device__ __forceinline__ void mma16(float* c, const unsigned* a,
                                      unsigned b0, unsigned b1) {
    asm volatile(
        "mma.sync.aligned.m16n8k16.row.col.f32.bf16.bf16.f32 "
        "{%0,%1,%2,%3}, {%4,%5,%6,%7}, {%8,%9}, {%0,%1,%2,%3};\n"
        : "+f"(c[0]), "+f"(c[1]), "+f"(c[2]), "+f"(c[3])
        : "r"(a[0]), "r"(a[1]), "r"(a[2]), "r"(a[3]), "r"(b0), "r"(b1));
}

#define KW 12   // padded u32 k-stride (8 used) -> conflict-free fragment loads

// ---------------------------------------------------------------------------
// F GEMM, 3-pass branch-free (gi tiles, n-cols 384..1151). R11-verbatim loop.
// n0 = (blockIdx.x + 3) * 128. Grid (6, 1024).
// ---------------------------------------------------------------------------
__global__ void __launch_bounds__(256, 2)
gemm_f_3p(const float* __restrict__ A,
          const unsigned* __restrict__ Bhi,
          const unsigned* __restrict__ Blo,
          const float* __restrict__ bias,
          float* __restrict__ C)
{
    const int K = DD, N = NCAT;
    __shared__ unsigned As_hi[2][128][KW];
    __shared__ unsigned As_lo[2][128][KW];
    __shared__ unsigned Bs_hi[2][128][KW];
    __shared__ unsigned Bs_lo[2][128][KW];

    const int tid  = threadIdx.x;
    const int warp = tid >> 5, lane = tid & 31;
    const int g = lane >> 2, t = lane & 3;
    const int wm = warp >> 1, wn = warp & 1;   // 4 x 2 warp grid

    const int n0 = (blockIdx.x + 3) * 128;
    const int m0 = blockIdx.y * 128;

    const int lrowA = tid >> 2;
    const int lcolA = (tid & 3) * 4;
    const int lc2   = (tid & 3) * 2;
    const int lrowB = tid >> 1;
    const int lcolB = (tid & 1) * 4;
    const int Khalf = K >> 1;

    float acc[2][8][4];
#pragma unroll
    for (int mt = 0; mt < 2; mt++)
#pragma unroll
        for (int nt = 0; nt < 8; nt++)
#pragma unroll
            for (int r = 0; r < 4; r++) acc[mt][nt][r] = 0.0f;

    {
#pragma unroll
        for (int i = 0; i < 2; i++) {
            float4 v = *(const float4*)(A + (size_t)(m0 + lrowA + i * 64) * K + lcolA);
            int row = lrowA + i * 64;
            unsigned h0, l0, h1, l1;
            split_pack(v.x, v.y, h0, l0);
            split_pack(v.z, v.w, h1, l1);
            As_hi[0][row][lc2] = h0; As_hi[0][row][lc2 + 1] = h1;
            As_lo[0][row][lc2] = l0; As_lo[0][row][lc2 + 1] = l1;
        }
        *(uint4*)&Bs_hi[0][lrowB][lcolB] =
            *(const uint4*)(Bhi + (size_t)(n0 + lrowB) * Khalf + lcolB);
        *(uint4*)&Bs_lo[0][lrowB][lcolB] =
            *(const uint4*)(Blo + (size_t)(n0 + lrowB) * Khalf + lcolB);
    }

    int cur = 0;
    for (int k0 = 0; k0 < K; k0 += 16) {
        __syncthreads();
        const bool hasNext = (k0 + 16 < K);

        float4 na[2];
        uint4 nbh, nbl;
        if (hasNext) {
            int koff = k0 + 16;
#pragma unroll
            for (int i = 0; i < 2; i++)
                na[i] = *(const float4*)(A + (size_t)(m0 + lrowA + i * 64) * K + koff + lcolA);
            nbh = *(const uint4*)(Bhi + (size_t)(n0 + lrowB) * Khalf + koff / 2 + lcolB);
            nbl = *(const uint4*)(Blo + (size_t)(n0 + lrowB) * Khalf + koff / 2 + lcolB);
        }

        unsigned ah[2][4], al[2][4];
#pragma unroll
        for (int mt = 0; mt < 2; mt++) {
            int mb = wm * 32 + mt * 16;
            ah[mt][0] = As_hi[cur][mb + g    ][t];
            ah[mt][1] = As_hi[cur][mb + g + 8][t];
            ah[mt][2] = As_hi[cur][mb + g    ][t + 4];
            ah[mt][3] = As_hi[cur][mb + g + 8][t + 4];
            al[mt][0] = As_lo[cur][mb + g    ][t];
            al[mt][1] = As_lo[cur][mb + g + 8][t];
            al[mt][2] = As_lo[cur][mb + g    ][t + 4];
            al[mt][3] = As_lo[cur][mb + g + 8][t + 4];
        }
#pragma unroll
        for (int nt = 0; nt < 8; nt++) {
            int nb = wn * 64 + nt * 8;
            unsigned bh0 = Bs_hi[cur][nb + g][t];
            unsigned bh1 = Bs_hi[cur][nb + g][t + 4];
            unsigned bl0 = Bs_lo[cur][nb + g][t];
            unsigned bl1 = Bs_lo[cur][nb + g][t + 4];
#pragma unroll
            for (int mt = 0; mt < 2; mt++) {
                mma16(acc[mt][nt], al[mt], bh0, bh1);
                mma16(acc[mt][nt], ah[mt], bl0, bl1);
                mma16(acc[mt][nt], ah[mt], bh0, bh1);
            }
        }

        if (hasNext) {
            int nxt = cur ^ 1;
#pragma unroll
            for (int i = 0; i < 2; i++) {
                int row = lrowA + i * 64;
                unsigned h0, l0, h1, l1;
                split_pack(na[i].x, na[i].y, h0, l0);
                split_pack(na[i].z, na[i].w, h1, l1);
                As_hi[nxt][row][lc2] = h0; As_hi[nxt][row][lc2 + 1] = h1;
                As_lo[nxt][row][lc2] = l0; As_lo[nxt][row][lc2 + 1] = l1;
            }
            *(uint4*)&Bs_hi[nxt][lrowB][lcolB] = nbh;
            *(uint4*)&Bs_lo[nxt][lrowB][lcolB] = nbl;
        }
        cur ^= 1;
    }

#pragma unroll
    for (int mt = 0; mt < 2; mt++) {
        int r0 = m0 + wm * 32 + mt * 16 + g;
#pragma unroll
        for (int nt = 0; nt < 8; nt++) {
            int col = n0 + wn * 64 + nt * 8 + 2 * t;
            float bv0 = bias[col], bv1 = bias[col + 1];
            float2 v;
            v.x = acc[mt][nt][0] + bv0; v.y = acc[mt][nt][1] + bv1;
            *(float2*)&C[(size_t)r0 * N + col] = v;
            v.x = acc[mt][nt][2] + bv0; v.y = acc[mt][nt][3] + bv1;
            *(float2*)&C[(size_t)(r0 + 8) * N + col] = v;
        }
    }
}

// ---------------------------------------------------------------------------
// F GEMM, 1-pass branch-free (hidden tiles, n-cols 0..383). hi*hi only:
// no lo staging, no lo loads, 1/3 the MMAs. Error ~2^-9 rel on logits path,
// validated at rel_err ~6e-5 in R9/R10. Grid (3, 1024).
// ---------------------------------------------------------------------------
__global__ void __launch_bounds__(256, 2)
gemm_f_1p(const float* __restrict__ A,
          const unsigned* __restrict__ Bhi,
          const float* __restrict__ bias,
          float* __restrict__ C)
{
    const int K = DD, N = NCAT;
    __shared__ unsigned As_hi[2][128][KW];
    __shared__ unsigned Bs_hi[2][128][KW];

    const int tid  = threadIdx.x;
    const int warp = tid >> 5, lane = tid & 31;
    const int g = lane >> 2, t = lane & 3;
    const int wm = warp >> 1, wn = warp & 1;

    const int n0 = blockIdx.x * 128;
    const int m0 = blockIdx.y * 128;

    const int lrowA = tid >> 2;
    const int lcolA = (tid & 3) * 4;
    const int lc2   = (tid & 3) * 2;
    const int lrowB = tid >> 1;
    const int lcolB = (tid & 1) * 4;
    const int Khalf = K >> 1;

    float acc[2][8][4];
#pragma unroll
    for (int mt = 0; mt < 2; mt++)
#pragma unroll
        for (int nt = 0; nt < 8; nt++)
#pragma unroll
            for (int r = 0; r < 4; r++) acc[mt][nt][r] = 0.0f;

    {
#pragma unroll
        for (int i = 0; i < 2; i++) {
            float4 v = *(const float4*)(A + (size_t)(m0 + lrowA + i * 64) * K + lcolA);
            int row = lrowA + i * 64;
            As_hi[0][row][lc2]     = pack_hi_only(v.x, v.y);
            As_hi[0][row][lc2 + 1] = pack_hi_only(v.z, v.w);
        }
        *(uint4*)&Bs_hi[0][lrowB][lcolB] =
            *(const uint4*)(Bhi + (size_t)(n0 + lrowB) * Khalf + lcolB);
    }

    int cur = 0;
    for (int k0 = 0; k0 < K; k0 += 16) {
        __syncthreads();
        const bool hasNext = (k0 + 16 < K);

        float4 na[2];
        uint4 nbh;
        if (hasNext) {
            int koff = k0 + 16;
#pragma unroll
            for (int i = 0; i < 2; i++)
                na[i] = *(const float4*)(A + (size_t)(m0 + lrowA + i * 64) * K + koff + lcolA);
            nbh = *(const uint4*)(Bhi + (size_t)(n0 + lrowB) * Khalf + koff / 2 + lcolB);
        }

        unsigned ah[2][4];
#pragma unroll
        for (int mt = 0; mt < 2; mt++) {
            int mb = wm * 32 + mt * 16;
            ah[mt][0] = As_hi[cur][mb + g    ][t];
            ah[mt][1] = As_hi[cur][mb + g + 8][t];
            ah[mt][2] = As_hi[cur][mb + g    ][t + 4];
            ah[mt][3] = As_hi[cur][mb + g + 8][t + 4];
        }
#pragma unroll
        for (int nt = 0; nt < 8; nt++) {
            int nb = wn * 64 + nt * 8;
            unsigned bh0 = Bs_hi[cur][nb + g][t];
            unsigned bh1 = Bs_hi[cur][nb + g][t + 4];
#pragma unroll
            for (int mt = 0; mt < 2; mt++)
                mma16(acc[mt][nt], ah[mt], bh0, bh1);
        }

        if (hasNext) {
            int nxt = cur ^ 1;
#pragma unroll
            for (int i = 0; i < 2; i++) {
                int row = lrowA + i * 64;
                As_hi[nxt][row][lc2]     = pack_hi_only(na[i].x, na[i].y);
                As_hi[nxt][row][lc2 + 1] = pack_hi_only(na[i].z, na[i].w);
            }
            *(uint4*)&Bs_hi[nxt][lrowB][lcolB] = nbh;
        }
        cur ^= 1;
    }

#pragma unroll
    for (int mt = 0; mt < 2; mt++) {
        int r0 = m0 + wm * 32 + mt * 16 + g;
#pragma unroll
        for (int nt = 0; nt < 8; nt++) {
            int col = n0 + wn * 64 + nt * 8 + 2 * t;
            float bv0 = bias[col], bv1 = bias[col + 1];
            float2 v;
            v.x = acc[mt][nt][0] + bv0; v.y = acc[mt][nt][1] + bv1;
            *(float2*)&C[(size_t)r0 * N + col] = v;
            v.x = acc[mt][nt][2] + bv0; v.y = acc[mt][nt][3] + bv1;
            *(float2*)&C[(size_t)(r0 + 8) * N + col] = v;
        }
    }
}

// ---------------------------------------------------------------------------
// Recurrent Zh GEMM: cp.async BK=32 (R15) + PASS-MAJOR MMA ordering:
// all B fragments for a k16 slab staged in regs, then the 48 MMAs issued
// pass-major so consecutive HMMAs hit different accumulators (16-deep ILP)
// instead of 3 back-to-back RAW-dependent MMAs per accumulator.
// ---------------------------------------------------------------------------
#define ZKW 20                         // u32 row stride (16 data + 4 pad)
#define ZARR ((size_t)2 * 128 * ZKW)   // u32 per operand array (both stages)
#define ZSTG ((size_t)128 * ZKW)       // u32 per stage

__device__ __forceinline__ void cp16(unsigned dst_smem, const void* src) {
    asm volatile("cp.async.ca.shared.global [%0], [%1], 16;"
                 :: "r"(dst_smem), "l"(src));
}
__device__ __forceinline__ unsigned smem_addr_u32(const void* p) {
    unsigned a;
    asm("{ .reg .u64 tmp; cvta.to.shared.u64 tmp, %1; cvt.u32.u64 %0, tmp; }"
        : "=r"(a) : "l"(p));
    return a;
}

__global__ void __launch_bounds__(256, 1)
gemm_zh(const unsigned* __restrict__ Ahi,
        const unsigned* __restrict__ Alo,
        const unsigned* __restrict__ Bhi,
        const unsigned* __restrict__ Blo,
        const float* __restrict__ bias,
        float* __restrict__ C)
{
    extern __shared__ unsigned zs[];
    unsigned* sAhi = zs;
    unsigned* sAlo = zs + ZARR;
    unsigned* sBhi = zs + 2 * ZARR;
    unsigned* sBlo = zs + 3 * ZARR;
    const unsigned smb = smem_addr_u32(zs);

    const int tid  = threadIdx.x;
    const int warp = tid >> 5, lane = tid & 31;
    const int g = lane >> 2, t = lane & 3;
    const int wm = warp >> 1, wn = warp & 1;   // 4 x 2 warp grid

    const int n0 = blockIdx.x * 128;
    const int m0 = blockIdx.y * 128;
    const int Khalf = SS / 2;            // 128 u32 per operand row

    const int lrow = tid >> 1;           // 0..127
    const int lc   = (tid & 1) * 8;      // u32 col within the 16-u32 stage

    const size_t srcA = (size_t)(m0 + lrow) * Khalf;
    const size_t srcB = (size_t)(n0 + lrow) * Khalf;
    const unsigned dstRow = (unsigned)(lrow * ZKW + lc);

    float acc[2][8][4];
#pragma unroll
    for (int mt = 0; mt < 2; mt++)
#pragma unroll
        for (int nt = 0; nt < 8; nt++)
#pragma unroll
            for (int r = 0; r < 4; r++) acc[mt][nt][r] = 0.0f;

    auto load_stage = [&](int buf, int ko) {
        unsigned base = smb + (unsigned)(buf * ZSTG + dstRow) * 4u;
        cp16(base + (unsigned)(0 * ZARR * 4), Ahi + srcA + ko + lc);
        cp16(base + (unsigned)(0 * ZARR * 4) + 16, Ahi + srcA + ko + lc + 4);
        cp16(base + (unsigned)(1 * ZARR * 4), Alo + srcA + ko + lc);
        cp16(base + (unsigned)(1 * ZARR * 4) + 16, Alo + srcA + ko + lc + 4);
        cp16(base + (unsigned)(2 * ZARR * 4), Bhi + srcB + ko + lc);
        cp16(base + (unsigned)(2 * ZARR * 4) + 16, Bhi + srcB + ko + lc + 4);
        cp16(base + (unsigned)(3 * ZARR * 4), Blo + srcB + ko + lc);
        cp16(base + (unsigned)(3 * ZARR * 4) + 16, Blo + srcB + ko + lc + 4);
        asm volatile("cp.async.commit_group;" ::: "memory");
    };

    load_stage(0, 0);

    int cur = 0;
    for (int it = 0; it < 8; it++) {           // 8 x BK=32
        asm volatile("cp.async.wait_group 0;" ::: "memory");
        __syncthreads();
        if (it + 1 < 8) load_stage(cur ^ 1, (it + 1) * 16);

        const unsigned* bA_hi = sAhi + cur * ZSTG;
        const unsigned* bA_lo = sAlo + cur * ZSTG;
        const unsigned* bB_hi = sBhi + cur * ZSTG;
        const unsigned* bB_lo = sBlo + cur * ZSTG;

#pragma unroll
        for (int kk = 0; kk < 16; kk += 8) {   // two k16 slabs
            unsigned ah[2][4], al[2][4];
#pragma unroll
            for (int mt = 0; mt < 2; mt++) {
                int mb = wm * 32 + mt * 16;
                ah[mt][0] = bA_hi[(mb + g    ) * ZKW + kk + t];
                ah[mt][1] = bA_hi[(mb + g + 8) * ZKW + kk + t];
                ah[mt][2] = bA_hi[(mb + g    ) * ZKW + kk + t + 4];
                ah[mt][3] = bA_hi[(mb + g + 8) * ZKW + kk + t + 4];
                al[mt][0] = bA_lo[(mb + g    ) * ZKW + kk + t];
                al[mt][1] = bA_lo[(mb + g + 8) * ZKW + kk + t];
                al[mt][2] = bA_lo[(mb + g    ) * ZKW + kk + t + 4];
                al[mt][3] = bA_lo[(mb + g + 8) * ZKW + kk + t + 4];
            }
            unsigned vbh0[8], vbh1[8], vbl0[8], vbl1[8];
#pragma unroll
            for (int nt = 0; nt < 8; nt++) {
                int nb = wn * 64 + nt * 8;
                vbh0[nt] = bB_hi[(nb + g) * ZKW + kk + t];
                vbh1[nt] = bB_hi[(nb + g) * ZKW + kk + t + 4];
                vbl0[nt] = bB_lo[(nb + g) * ZKW + kk + t];
                vbl1[nt] = bB_lo[(nb + g) * ZKW + kk + t + 4];
            }
            // pass 1: al * bh  (all 16 MMAs independent)
#pragma unroll
            for (int nt = 0; nt < 8; nt++)
#pragma unroll
                for (int mt = 0; mt < 2; mt++)
                    mma16(acc[mt][nt], al[mt], vbh0[nt], vbh1[nt]);
            // pass 2: ah * bl
#pragma unroll
            for (int nt = 0; nt < 8; nt++)
#pragma unroll
                for (int mt = 0; mt < 2; mt++)
                    mma16(acc[mt][nt], ah[mt], vbl0[nt], vbl1[nt]);
            // pass 3: ah * bh
#pragma unroll
            for (int nt = 0; nt < 8; nt++)
#pragma unroll
                for (int mt = 0; mt < 2; mt++)
                    mma16(acc[mt][nt], ah[mt], vbh0[nt], vbh1[nt]);
        }
        __syncthreads();
        cur ^= 1;
    }

#pragma unroll
    for (int mt = 0; mt < 2; mt++) {
        int r0 = m0 + wm * 32 + mt * 16 + g;
#pragma unroll
        for (int nt = 0; nt < 8; nt++) {
            int col = n0 + wn * 64 + nt * 8 + 2 * t;
            float bv0 = bias[col], bv1 = bias[col + 1];
            float2 v;
            v.x = acc[mt][nt][0] + bv0; v.y = acc[mt][nt][1] + bv1;
            *(float2*)&C[(size_t)r0 * NCAT + col] = v;
            v.x = acc[mt][nt][2] + bv0; v.y = acc[mt][nt][3] + bv1;
            *(float2*)&C[(size_t)(r0 + 8) * NCAT + col] = v;
        }
    }
}
#define ZH_SMEM_BYTES ((int)(4 * ZARR * 4))   // 81920

// ---------------------------------------------------------------------------
// Per-step fusion (R11/R15, measured-best): block-per-row, 256 threads.
// ---------------------------------------------------------------------------
__global__ void __launch_bounds__(256)
step_kernel(int t,
            const float* __restrict__ gum,
            const float* __restrict__ W2,
            const float* __restrict__ b2,
            const float* __restrict__ temp_ptr,
            const float* __restrict__ wpos,
            const float* __restrict__ F,
            const float* __restrict__ Zh,
            unsigned* __restrict__ h_hi,
            unsigned* __restrict__ h_lo,
            float* __restrict__ out_pos,
            float* __restrict__ out_states,
            float* __restrict__ out_hfinal)
{
    const int b = blockIdx.x;
    const int tid = threadIdx.x;
    const int warp = tid >> 5, lane = tid & 31;
    const size_t bt = (size_t)b * TT + t;

    __shared__ float sh_hidden[HH1];
    __shared__ float sh_logits[PP];
    __shared__ float sh_pos;

    const float* Frow = F + bt * NCAT;
    const float* Zrow = Zh + (size_t)b * NCAT;

    const int j = tid;   // 0..255 == SS
    __nv_bfloat16 hold_hi = ((const __nv_bfloat16*)h_hi)[(size_t)b * SS + j];
    __nv_bfloat16 hold_lo = ((const __nv_bfloat16*)h_lo)[(size_t)b * SS + j];
    float f_r = Frow[HH1 + j];
    float f_z = Frow[HH1 + SS + j];
    float f_n = Frow[HH1 + 2 * SS + j];
    float z_r = Zrow[HH1 + j];
    float z_z = Zrow[HH1 + SS + j];
    float z_n = Zrow[HH1 + 2 * SS + j];
    float wp_r = wpos[j];
    float wp_z = wpos[SS + j];
    float wp_n = wpos[2 * SS + j];

    float2 hf2, hz2;
    if (tid < 192) {
        hf2 = ((const float2*)Frow)[tid];
        hz2 = ((const float2*)Zrow)[tid];
    }

    float gv = 0.0f, temp = 1.0f;
    if (warp == 0) {
        temp = *temp_ptr;
        if (lane < PP) gv = gum[bt * PP + lane];
    }

    if (tid < 192) {
        float2 r;
        r.x = fmaxf(hf2.x + hz2.x, 0.0f);
        r.y = fmaxf(hf2.y + hz2.y, 0.0f);
        ((float2*)sh_hidden)[tid] = r;
    }
    __syncthreads();

    {
        const float4* h4 = (const float4*)sh_hidden;
        const float4* W2a = (const float4*)(W2 + warp * HH1);
        float s = 0.0f;
#pragma unroll
        for (int i = 0; i < 3; i++) {
            float4 w = W2a[lane + 32 * i], hh = h4[lane + 32 * i];
            s = fmaf(w.x, hh.x, s); s = fmaf(w.y, hh.y, s);
            s = fmaf(w.z, hh.z, s); s = fmaf(w.w, hh.w, s);
        }
#pragma unroll
        for (int off = 16; off > 0; off >>= 1)
            s += __shfl_xor_sync(0xffffffffu, s, off);
        if (lane == 0) sh_logits[warp] = s + b2[warp];

        if (warp < 3) {
            const float4* W2b = (const float4*)(W2 + (warp + 8) * HH1);
            float s2 = 0.0f;
#pragma unroll
            for (int i = 0; i < 3; i++) {
                float4 w = W2b[lane + 32 * i], hh = h4[lane + 32 * i];
                s2 = fmaf(w.x, hh.x, s2); s2 = fmaf(w.y, hh.y, s2);
                s2 = fmaf(w.z, hh.z, s2); s2 = fmaf(w.w, hh.w, s2);
            }
#pragma unroll
            for (int off = 16; off > 0; off >>= 1)
                s2 += __shfl_xor_sync(0xffffffffu, s2, off);
            if (lane == 0) sh_logits[warp + 8] = s2 + b2[warp + 8];
        }
    }
    __syncthreads();

    if (warp == 0) {
        float val = -INFINITY;
        if (lane < PP) val = (sh_logits[lane] + gv) / temp;
        float m = val;
#pragma unroll
        for (int off = 16; off > 0; off >>= 1)
            m = fmaxf(m, __shfl_xor_sync(0xffffffffu, m, off));
        float e = (lane < PP) ? __expf(val - m) : 0.0f;
        float s = e;
        float w = (lane < PP) ? e * (float)lane : 0.0f;
#pragma unroll
        for (int off = 16; off > 0; off >>= 1) {
            s += __shfl_xor_sync(0xffffffffu, s, off);
            w += __shfl_xor_sync(0xffffffffu, w, off);
        }
        if (lane == 0) {
            float pos = w / s;
            sh_pos = pos;
            out_pos[bt] = pos;
        }
    }
    __syncthreads();
    const float pos = sh_pos;

    float hold = __bfloat162float(hold_hi) + __bfloat162float(hold_lo);
    float gi_r = f_r + pos * wp_r;
    float gi_z = f_z + pos * wp_z;
    float gi_n = f_n + pos * wp_n;

    float r = 1.0f / (1.0f + __expf(-(gi_r + z_r)));
    float z = 1.0f / (1.0f + __expf(-(gi_z + z_z)));
    float xn = gi_n + r * z_n;
    float n = 1.0f - 2.0f / (__expf(2.0f * xn) + 1.0f);
    float hnew = (1.0f - z) * n + z * hold;

    {
        __nv_bfloat16 bh = __float2bfloat16(hnew);
        ((__nv_bfloat16*)h_hi)[(size_t)b * SS + j] = bh;
        ((__nv_bfloat16*)h_lo)[(size_t)b * SS + j] =
            __float2bfloat16(hnew - __bfloat162float(bh));
    }
    out_states[bt * SS + j] = hnew;
    if (t == TT - 1) out_hfinal[(size_t)b * SS + j] = hnew;
}

// ---------------------------------------------------------------------------
extern "C" void kernel_launch(void* const* d_in, const int* in_sizes, int n_in,
                              void* d_out, int out_size)
{
    const float* price = (const float*)d_in[0];
    const float* u     = (const float*)d_in[1];
    const float* W1    = (const float*)d_in[2];
    const float* b1    = (const float*)d_in[3];
    const float* W2    = (const float*)d_in[4];
    const float* b2    = (const float*)d_in[5];
    const float* temp  = (const float*)d_in[6];
    const float* W_ih  = (const float*)d_in[7];
    const float* b_ih  = (const float*)d_in[8];
    const float* W_hh  = (const float*)d_in[9];
    const float* b_hh  = (const float*)d_in[10];
    const float* h0    = (const float*)d_in[11];

    float* scratch = nullptr;
    cudaGetSymbolAddress((void**)&scratch, g_scratch);
    float* F      = scratch + OFF_F;
    float* Zh     = scratch + OFF_ZH;
    float* gum    = scratch + OFF_GUM;
    float* wpos   = scratch + OFF_WPOS;
    float* bf     = scratch + OFF_BF;
    float* bzh    = scratch + OFF_BZH;
    unsigned* Wfhi = (unsigned*)(scratch + OFF_WFHI);
    unsigned* Wflo = (unsigned*)(scratch + OFF_WFLO);
    unsigned* Whhi = (unsigned*)(scratch + OFF_WHHI);
    unsigned* Whlo = (unsigned*)(scratch + OFF_WHLO);
    unsigned* h_hi = (unsigned*)(scratch + OFF_HHI);
    unsigned* h_lo = (unsigned*)(scratch + OFF_HLO);

    float* out        = (float*)d_out;
    float* out_pos    = out;                                  // [B, T]
    float* out_states = out + (size_t)BB * TT;                // [B, T, S]
    float* out_hf     = out_states + (size_t)BB * TT * SS;    // [B, S]

    cudaFuncSetAttribute(gemm_zh,
                         cudaFuncAttributeMaxDynamicSharedMemorySize,
                         ZH_SMEM_BYTES);

    // 1. pack + gumbel precompute
    pack_kernel<<<(BB * SS + 255) / 256, 256>>>(W1, b1, W_ih, b_ih, W_hh, b_hh,
                                                h0, Wfhi, Wflo, Whhi, Whlo,
                                                bf, bzh, h_hi, h_lo, wpos);
    gumbel_kernel<<<(BB * TT * PP + 255) / 256, 256>>>(u, gum);

    // 2. F GEMM split: 1-pass hidden tiles + 3-pass gi tiles (branch-free)
    {
        dim3 grid1(3, (BB * TT) / 128);   // hidden cols 0..383
        gemm_f_1p<<<grid1, 256>>>(price, Wfhi, bf, F);
        dim3 grid3(6, (BB * TT) / 128);   // gi cols 384..1151
        gemm_f_3p<<<grid3, 256>>>(price, Wfhi, Wflo, bf, F);
    }

    // 3. sequential recurrence: cp.async BK=32 pass-major Zh + step
    for (int t = 0; t < TT; t++) {
        dim3 grid(NCAT / 128, BB / 128);          // (9, 16) = 144 blocks
        gemm_zh<<<grid, 256, ZH_SMEM_BYTES>>>(h_hi, h_lo, Whhi, Whlo, bzh, Zh);
        step_kernel<<<BB, 256>>>(t, gum, W2, b2, temp, wpos,
                                 F, Zh, h_hi, h_lo,
                                 out_pos, out_states, out_hf);
    }
}

// round 17
// speedup vs baseline: 1.3050x; 1.0896x over previous
#include <cuda_runtime.h>
#include <cuda_bf16.h>
#include <math.h>
#include <stdint.h>

// Problem dims
#define BB 2048
#define TT 64
#define DD 512
#define SS 256
#define PP 11
#define HH1 384
#define NCAT 1152   // HH1 + 3*SS

// Scratch layout (float units) in one __device__ array
#define OFF_F    ((size_t)0)                          // [B*T, NCAT] (b-major)
#define SZ_F     ((size_t)BB * TT * NCAT)
#define OFF_ZH   (OFF_F + SZ_F)                       // [B, NCAT]
#define SZ_ZH    ((size_t)BB * NCAT)
#define OFF_GUM  (OFF_ZH + SZ_ZH)                     // [B*T*P] gumbel noise
#define SZ_GUM   ((size_t)BB * TT * PP)
#define OFF_WPOS (OFF_GUM + SZ_GUM)                   // [3*S]
#define SZ_WPOS  ((size_t)768)
#define OFF_BF   (OFF_WPOS + SZ_WPOS)                 // [NCAT] bias for F
#define SZ_BF    ((size_t)1280)
#define OFF_BZH  (OFF_BF + SZ_BF)                     // [NCAT] bias for Zh
#define SZ_BZH   ((size_t)1280)
#define OFF_WFHI (OFF_BZH + SZ_BZH)                   // u32 [NCAT][DD/2]
#define SZ_WFHI  ((size_t)NCAT * DD / 2)
#define OFF_WFLO (OFF_WFHI + SZ_WFHI)
#define OFF_WHHI (OFF_WFLO + SZ_WFHI)                 // u32 [NCAT][SS/2]
#define SZ_WHHI  ((size_t)NCAT * SS / 2)
#define OFF_WHLO (OFF_WHHI + SZ_WHHI)
#define OFF_HHI  (OFF_WHLO + SZ_WHHI)                 // u32 [B][SS/2] bf16 pairs
#define SZ_HHI   ((size_t)BB * SS / 2)
#define OFF_HLO  (OFF_HHI + SZ_HHI)
#define SCRATCH_TOTAL (OFF_HLO + SZ_HHI)

__device__ float g_scratch[SCRATCH_TOTAL];

// ---------------------------------------------------------------------------
__device__ __forceinline__ void split_pack(float x, float y,
                                           unsigned& hi, unsigned& lo) {
    __nv_bfloat162 h2 = __float22bfloat162_rn(make_float2(x, y));
    float rx = x - __bfloat162float(h2.x);
    float ry = y - __bfloat162float(h2.y);
    __nv_bfloat162 l2 = __float22bfloat162_rn(make_float2(rx, ry));
    hi = reinterpret_cast<unsigned&>(h2);
    lo = reinterpret_cast<unsigned&>(l2);
}
__device__ __forceinline__ unsigned pack_hi_only(float x, float y) {
    __nv_bfloat162 h2 = __float22bfloat162_rn(make_float2(x, y));
    return reinterpret_cast<unsigned&>(h2);
}
__device__ __forceinline__ unsigned smem_addr_u32(const void* p) {
    unsigned a;
    asm("{ .reg .u64 tmp; cvta.to.shared.u64 tmp, %1; cvt.u32.u64 %0, tmp; }"
        : "=r"(a) : "l"(p));
    return a;
}
__device__ __forceinline__ void ldm_x4(unsigned& r0, unsigned& r1,
                                       unsigned& r2, unsigned& r3,
                                       unsigned addr) {
    asm volatile("ldmatrix.sync.aligned.m8n8.x4.shared.b16 {%0,%1,%2,%3}, [%4];"
                 : "=r"(r0), "=r"(r1), "=r"(r2), "=r"(r3) : "r"(addr));
}

// ---------------------------------------------------------------------------
// Pack kernel: pre-split fused weights to bf16 hi/lo, biases, wpos, h init
// ---------------------------------------------------------------------------
__global__ void pack_kernel(const float* __restrict__ W1,
                            const float* __restrict__ b1,
                            const float* __restrict__ W_ih,
                            const float* __restrict__ b_ih,
                            const float* __restrict__ W_hh,
                            const float* __restrict__ b_hh,
                            const float* __restrict__ h0,
                            unsigned* __restrict__ Wfhi,
                            unsigned* __restrict__ Wflo,
                            unsigned* __restrict__ Whhi,
                            unsigned* __restrict__ Whlo,
                            float* __restrict__ bf,
                            float* __restrict__ bzh,
                            unsigned* __restrict__ h_hi,
                            unsigned* __restrict__ h_lo,
                            float* __restrict__ wpos)
{
    int i = blockIdx.x * blockDim.x + threadIdx.x;
    if (i < NCAT * DD / 2) {
        int n = i / (DD / 2), kp = i % (DD / 2);
        int k0 = 2 * kp;
        float v0, v1;
        if (n < HH1) {
            v0 = W1[n * (DD + SS) + k0];
            v1 = W1[n * (DD + SS) + k0 + 1];
        } else {
            v0 = W_ih[(size_t)(n - HH1) * (DD + 1) + k0];
            v1 = W_ih[(size_t)(n - HH1) * (DD + 1) + k0 + 1];
        }
        unsigned hi, lo;
        split_pack(v0, v1, hi, lo);
        Wfhi[i] = hi; Wflo[i] = lo;
    }
    if (i < NCAT * SS / 2) {
        int n = i / (SS / 2), kp = i % (SS / 2);
        int k0 = 2 * kp;
        float v0, v1;
        if (n < HH1) {
            v0 = W1[n * (DD + SS) + DD + k0];
            v1 = W1[n * (DD + SS) + DD + k0 + 1];
        } else {
            v0 = W_hh[(n - HH1) * SS + k0];
            v1 = W_hh[(n - HH1) * SS + k0 + 1];
        }
        unsigned hi, lo;
        split_pack(v0, v1, hi, lo);
        Whhi[i] = hi; Whlo[i] = lo;
    }
    if (i < NCAT) {
        bf[i]  = (i < HH1) ? b1[i] : b_ih[i - HH1];
        bzh[i] = (i < HH1) ? 0.0f : b_hh[i - HH1];
    }
    if (i < BB * SS) {
        float v = h0[i % SS];
        __nv_bfloat16 bh = __float2bfloat16(v);
        ((__nv_bfloat16*)h_hi)[i] = bh;
        ((__nv_bfloat16*)h_lo)[i] = __float2bfloat16(v - __bfloat162float(bh));
    }
    if (i < 3 * SS) wpos[i] = W_ih[(size_t)i * (DD + 1) + DD];
}

// ---------------------------------------------------------------------------
// Gumbel precompute
// ---------------------------------------------------------------------------
__global__ void gumbel_kernel(const float* __restrict__ u,
                              float* __restrict__ gum)
{
    int i = blockIdx.x * blockDim.x + threadIdx.x;
    if (i < BB * TT * PP) {
        float uu = u[i];
        gum[i] = -logf(-logf(uu + 1e-20f) + 1e-20f);
    }
}

// ---------------------------------------------------------------------------
__device__ __forceinline__ void mma16(float* c, const unsigned* a,
                                      unsigned b0, unsigned b1) {
    asm volatile(
        "mma.sync.aligned.m16n8k16.row.col.f32.bf16.bf16.f32 "
        "{%0,%1,%2,%3}, {%4,%5,%6,%7}, {%8,%9}, {%0,%1,%2,%3};\n"
        : "+f"(c[0]), "+f"(c[1]), "+f"(c[2]), "+f"(c[3])
        : "r"(a[0]), "r"(a[1]), "r"(a[2]), "r"(a[3]), "r"(b0), "r"(b1));
}

#define KW 12   // padded u32 k-stride; 48B rows sweep all banks for ldmatrix

// ---------------------------------------------------------------------------
// F GEMM, 3-pass branch-free (gi tiles, n-cols 384..1151), ldmatrix fragments.
// n0 = (blockIdx.x + 3) * 128. Grid (6, 1024).
// ---------------------------------------------------------------------------
__global__ void __launch_bounds__(256, 2)
gemm_f_3p(const float* __restrict__ A,
          const unsigned* __restrict__ Bhi,
          const unsigned* __restrict__ Blo,
          const float* __restrict__ bias,
          float* __restrict__ C)
{
    const int K = DD, N = NCAT;
    __shared__ unsigned As_hi[2][128][KW];
    __shared__ unsigned As_lo[2][128][KW];
    __shared__ unsigned Bs_hi[2][128][KW];
    __shared__ unsigned Bs_lo[2][128][KW];

    const int tid  = threadIdx.x;
    const int warp = tid >> 5, lane = tid & 31;
    const int g = lane >> 2, t = lane & 3;
    const int wm = warp >> 1, wn = warp & 1;   // 4 x 2 warp grid

    const int n0 = (blockIdx.x + 3) * 128;
    const int m0 = blockIdx.y * 128;

    const int lrowA = tid >> 2;
    const int lcolA = (tid & 3) * 4;
    const int lc2   = (tid & 3) * 2;
    const int lrowB = tid >> 1;
    const int lcolB = (tid & 1) * 4;
    const int Khalf = K >> 1;

    // ldmatrix per-lane offsets (bytes), relative to a buffer base
    const int idx  = lane & 7;
    const int ph01 = (lane >> 3) & 1;
    const int ph2  = lane >> 4;
    const unsigned aOff = (unsigned)((wm * 32 + ph01 * 8 + idx) * (KW * 4) + ph2 * 16);
    const unsigned bOff = (unsigned)((wn * 64 + ph2 * 8 + idx) * (KW * 4) + ph01 * 16);
    const unsigned aHiB = smem_addr_u32(As_hi);
    const unsigned aLoB = smem_addr_u32(As_lo);
    const unsigned bHiB = smem_addr_u32(Bs_hi);
    const unsigned bLoB = smem_addr_u32(Bs_lo);
    const unsigned BUFO = 128 * KW * 4;

    float acc[2][8][4];
#pragma unroll
    for (int mt = 0; mt < 2; mt++)
#pragma unroll
        for (int nt = 0; nt < 8; nt++)
#pragma unroll
            for (int r = 0; r < 4; r++) acc[mt][nt][r] = 0.0f;

    {
#pragma unroll
        for (int i = 0; i < 2; i++) {
            float4 v = *(const float4*)(A + (size_t)(m0 + lrowA + i * 64) * K + lcolA);
            int row = lrowA + i * 64;
            unsigned h0, l0, h1, l1;
            split_pack(v.x, v.y, h0, l0);
            split_pack(v.z, v.w, h1, l1);
            As_hi[0][row][lc2] = h0; As_hi[0][row][lc2 + 1] = h1;
            As_lo[0][row][lc2] = l0; As_lo[0][row][lc2 + 1] = l1;
        }
        *(uint4*)&Bs_hi[0][lrowB][lcolB] =
            *(const uint4*)(Bhi + (size_t)(n0 + lrowB) * Khalf + lcolB);
        *(uint4*)&Bs_lo[0][lrowB][lcolB] =
            *(const uint4*)(Blo + (size_t)(n0 + lrowB) * Khalf + lcolB);
    }

    int cur = 0;
    for (int k0 = 0; k0 < K; k0 += 16) {
        __syncthreads();
        const bool hasNext = (k0 + 16 < K);

        float4 na[2];
        uint4 nbh, nbl;
        if (hasNext) {
            int koff = k0 + 16;
#pragma unroll
            for (int i = 0; i < 2; i++)
                na[i] = *(const float4*)(A + (size_t)(m0 + lrowA + i * 64) * K + koff + lcolA);
            nbh = *(const uint4*)(Bhi + (size_t)(n0 + lrowB) * Khalf + koff / 2 + lcolB);
            nbl = *(const uint4*)(Blo + (size_t)(n0 + lrowB) * Khalf + koff / 2 + lcolB);
        }

        const unsigned bo = cur * BUFO;
        unsigned ah[2][4], al[2][4];
        ldm_x4(ah[0][0], ah[0][1], ah[0][2], ah[0][3], aHiB + bo + aOff);
        ldm_x4(ah[1][0], ah[1][1], ah[1][2], ah[1][3], aHiB + bo + aOff + 16 * KW * 4);
        ldm_x4(al[0][0], al[0][1], al[0][2], al[0][3], aLoB + bo + aOff);
        ldm_x4(al[1][0], al[1][1], al[1][2], al[1][3], aLoB + bo + aOff + 16 * KW * 4);

#pragma unroll
        for (int ntp = 0; ntp < 4; ntp++) {
            unsigned bh[4], bl[4];
            ldm_x4(bh[0], bh[1], bh[2], bh[3], bHiB + bo + bOff + ntp * 16 * KW * 4);
            ldm_x4(bl[0], bl[1], bl[2], bl[3], bLoB + bo + bOff + ntp * 16 * KW * 4);
#pragma unroll
            for (int h = 0; h < 2; h++) {
                int nt = 2 * ntp + h;
#pragma unroll
                for (int mt = 0; mt < 2; mt++) {
                    mma16(acc[mt][nt], al[mt], bh[2 * h], bh[2 * h + 1]);
                    mma16(acc[mt][nt], ah[mt], bl[2 * h], bl[2 * h + 1]);
                    mma16(acc[mt][nt], ah[mt], bh[2 * h], bh[2 * h + 1]);
                }
            }
        }

        if (hasNext) {
            int nxt = cur ^ 1;
#pragma unroll
            for (int i = 0; i < 2; i++) {
                int row = lrowA + i * 64;
                unsigned h0, l0, h1, l1;
                split_pack(na[i].x, na[i].y, h0, l0);
                split_pack(na[i].z, na[i].w, h1, l1);
                As_hi[nxt][row][lc2] = h0; As_hi[nxt][row][lc2 + 1] = h1;
                As_lo[nxt][row][lc2] = l0; As_lo[nxt][row][lc2 + 1] = l1;
            }
            *(uint4*)&Bs_hi[nxt][lrowB][lcolB] = nbh;
            *(uint4*)&Bs_lo[nxt][lrowB][lcolB] = nbl;
        }
        cur ^= 1;
    }

#pragma unroll
    for (int mt = 0; mt < 2; mt++) {
        int r0 = m0 + wm * 32 + mt * 16 + g;
#pragma unroll
        for (int nt = 0; nt < 8; nt++) {
            int col = n0 + wn * 64 + nt * 8 + 2 * t;
            float bv0 = bias[col], bv1 = bias[col + 1];
            float2 v;
            v.x = acc[mt][nt][0] + bv0; v.y = acc[mt][nt][1] + bv1;
            *(float2*)&C[(size_t)r0 * N + col] = v;
            v.x = acc[mt][nt][2] + bv0; v.y = acc[mt][nt][3] + bv1;
            *(float2*)&C[(size_t)(r0 + 8) * N + col] = v;
        }
    }
}

// ---------------------------------------------------------------------------
// F GEMM, 1-pass branch-free (hidden tiles, n-cols 0..383), ldmatrix.
// ---------------------------------------------------------------------------
__global__ void __launch_bounds__(256, 2)
gemm_f_1p(const float* __restrict__ A,
          const unsigned* __restrict__ Bhi,
          const float* __restrict__ bias,
          float* __restrict__ C)
{
    const int K = DD, N = NCAT;
    __shared__ unsigned As_hi[2][128][KW];
    __shared__ unsigned Bs_hi[2][128][KW];

    const int tid  = threadIdx.x;
    const int warp = tid >> 5, lane = tid & 31;
    const int g = lane >> 2, t = lane & 3;
    const int wm = warp >> 1, wn = warp & 1;

    const int n0 = blockIdx.x * 128;
    const int m0 = blockIdx.y * 128;

    const int lrowA = tid >> 2;
    const int lcolA = (tid & 3) * 4;
    const int lc2   = (tid & 3) * 2;
    const int lrowB = tid >> 1;
    const int lcolB = (tid & 1) * 4;
    const int Khalf = K >> 1;

    const int idx  = lane & 7;
    const int ph01 = (lane >> 3) & 1;
    const int ph2  = lane >> 4;
    const unsigned aOff = (unsigned)((wm * 32 + ph01 * 8 + idx) * (KW * 4) + ph2 * 16);
    const unsigned bOff = (unsigned)((wn * 64 + ph2 * 8 + idx) * (KW * 4) + ph01 * 16);
    const unsigned aHiB = smem_addr_u32(As_hi);
    const unsigned bHiB = smem_addr_u32(Bs_hi);
    const unsigned BUFO = 128 * KW * 4;

    float acc[2][8][4];
#pragma unroll
    for (int mt = 0; mt < 2; mt++)
#pragma unroll
        for (int nt = 0; nt < 8; nt++)
#pragma unroll
            for (int r = 0; r < 4; r++) acc[mt][nt][r] = 0.0f;

    {
#pragma unroll
        for (int i = 0; i < 2; i++) {
            float4 v = *(const float4*)(A + (size_t)(m0 + lrowA + i * 64) * K + lcolA);
            int row = lrowA + i * 64;
            As_hi[0][row][lc2]     = pack_hi_only(v.x, v.y);
            As_hi[0][row][lc2 + 1] = pack_hi_only(v.z, v.w);
        }
        *(uint4*)&Bs_hi[0][lrowB][lcolB] =
            *(const uint4*)(Bhi + (size_t)(n0 + lrowB) * Khalf + lcolB);
    }

    int cur = 0;
    for (int k0 = 0; k0 < K; k0 += 16) {
        __syncthreads();
        const bool hasNext = (k0 + 16 < K);

        float4 na[2];
        uint4 nbh;
        if (hasNext) {
            int koff = k0 + 16;
#pragma unroll
            for (int i = 0; i < 2; i++)
                na[i] = *(const float4*)(A + (size_t)(m0 + lrowA + i * 64) * K + koff + lcolA);
            nbh = *(const uint4*)(Bhi + (size_t)(n0 + lrowB) * Khalf + koff / 2 + lcolB);
        }

        const unsigned bo = cur * BUFO;
        unsigned ah[2][4];
        ldm_x4(ah[0][0], ah[0][1], ah[0][2], ah[0][3], aHiB + bo + aOff);
        ldm_x4(ah[1][0], ah[1][1], ah[1][2], ah[1][3], aHiB + bo + aOff + 16 * KW * 4);

#pragma unroll
        for (int ntp = 0; ntp < 4; ntp++) {
            unsigned bh[4];
            ldm_x4(bh[0], bh[1], bh[2], bh[3], bHiB + bo + bOff + ntp * 16 * KW * 4);
#pragma unroll
            for (int h = 0; h < 2; h++) {
                int nt = 2 * ntp + h;
#pragma unroll
                for (int mt = 0; mt < 2; mt++)
                    mma16(acc[mt][nt], ah[mt], bh[2 * h], bh[2 * h + 1]);
            }
        }

        if (hasNext) {
            int nxt = cur ^ 1;
#pragma unroll
            for (int i = 0; i < 2; i++) {
                int row = lrowA + i * 64;
                As_hi[nxt][row][lc2]     = pack_hi_only(na[i].x, na[i].y);
                As_hi[nxt][row][lc2 + 1] = pack_hi_only(na[i].z, na[i].w);
            }
            *(uint4*)&Bs_hi[nxt][lrowB][lcolB] = nbh;
        }
        cur ^= 1;
    }

#pragma unroll
    for (int mt = 0; mt < 2; mt++) {
        int r0 = m0 + wm * 32 + mt * 16 + g;
#pragma unroll
        for (int nt = 0; nt < 8; nt++) {
            int col = n0 + wn * 64 + nt * 8 + 2 * t;
            float bv0 = bias[col], bv1 = bias[col + 1];
            float2 v;
            v.x = acc[mt][nt][0] + bv0; v.y = acc[mt][nt][1] + bv1;
            *(float2*)&C[(size_t)r0 * N + col] = v;
            v.x = acc[mt][nt][2] + bv0; v.y = acc[mt][nt][3] + bv1;
            *(float2*)&C[(size_t)(r0 + 8) * N + col] = v;
        }
    }
}

// ---------------------------------------------------------------------------
// Recurrent Zh GEMM: cp.async BK=32 + ldmatrix fragments + pass-major MMAs.
// ---------------------------------------------------------------------------
#define ZKW 20                         // u32 row stride; 80B rows sweep banks
#define ZARR ((size_t)2 * 128 * ZKW)   // u32 per operand array (both stages)
#define ZSTG ((size_t)128 * ZKW)       // u32 per stage

__device__ __forceinline__ void cp16(unsigned dst_smem, const void* src) {
    asm volatile("cp.async.ca.shared.global [%0], [%1], 16;"
                 :: "r"(dst_smem), "l"(src));
}

__global__ void __launch_bounds__(256, 1)
gemm_zh(const unsigned* __restrict__ Ahi,
        const unsigned* __restrict__ Alo,
        const unsigned* __restrict__ Bhi,
        const unsigned* __restrict__ Blo,
        const float* __restrict__ bias,
        float* __restrict__ C)
{
    extern __shared__ unsigned zs[];
    const unsigned smb = smem_addr_u32(zs);
    const unsigned aHiB = smb;
    const unsigned aLoB = smb + (unsigned)(ZARR * 4);
    const unsigned bHiB = smb + (unsigned)(2 * ZARR * 4);
    const unsigned bLoB = smb + (unsigned)(3 * ZARR * 4);

    const int tid  = threadIdx.x;
    const int warp = tid >> 5, lane = tid & 31;
    const int g = lane >> 2, t = lane & 3;
    const int wm = warp >> 1, wn = warp & 1;   // 4 x 2 warp grid

    const int n0 = blockIdx.x * 128;
    const int m0 = blockIdx.y * 128;
    const int Khalf = SS / 2;            // 128 u32 per operand row

    const int lrow = tid >> 1;           // 0..127
    const int lc   = (tid & 1) * 8;      // u32 col within the 16-u32 stage

    const size_t srcA = (size_t)(m0 + lrow) * Khalf;
    const size_t srcB = (size_t)(n0 + lrow) * Khalf;
    const unsigned dstRow = (unsigned)(lrow * ZKW + lc);

    const int idx  = lane & 7;
    const int ph01 = (lane >> 3) & 1;
    const int ph2  = lane >> 4;
    const unsigned aOff = (unsigned)((wm * 32 + ph01 * 8 + idx) * (ZKW * 4) + ph2 * 16);
    const unsigned bOff = (unsigned)((wn * 64 + ph2 * 8 + idx) * (ZKW * 4) + ph01 * 16);

    float acc[2][8][4];
#pragma unroll
    for (int mt = 0; mt < 2; mt++)
#pragma unroll
        for (int nt = 0; nt < 8; nt++)
#pragma unroll
            for (int r = 0; r < 4; r++) acc[mt][nt][r] = 0.0f;

    auto load_stage = [&](int buf, int ko) {
        unsigned base = smb + (unsigned)(buf * ZSTG + dstRow) * 4u;
        cp16(base + (unsigned)(0 * ZARR * 4), Ahi + srcA + ko + lc);
        cp16(base + (unsigned)(0 * ZARR * 4) + 16, Ahi + srcA + ko + lc + 4);
        cp16(base + (unsigned)(1 * ZARR * 4), Alo + srcA + ko + lc);
        cp16(base + (unsigned)(1 * ZARR * 4) + 16, Alo + srcA + ko + lc + 4);
        cp16(base + (unsigned)(2 * ZARR * 4), Bhi + srcB + ko + lc);
        cp16(base + (unsigned)(2 * ZARR * 4) + 16, Bhi + srcB + ko + lc + 4);
        cp16(base + (unsigned)(3 * ZARR * 4), Blo + srcB + ko + lc);
        cp16(base + (unsigned)(3 * ZARR * 4) + 16, Blo + srcB + ko + lc + 4);
        asm volatile("cp.async.commit_group;" ::: "memory");
    };

    load_stage(0, 0);

    int cur = 0;
    for (int it = 0; it < 8; it++) {           // 8 x BK=32
        asm volatile("cp.async.wait_group 0;" ::: "memory");
        __syncthreads();
        if (it + 1 < 8) load_stage(cur ^ 1, (it + 1) * 16);

        const unsigned so = (unsigned)(cur * ZSTG * 4);

#pragma unroll
        for (int kk = 0; kk < 16; kk += 8) {   // two k16 slabs
            const unsigned kb = kk * 4;
            unsigned ah[2][4], al[2][4];
            ldm_x4(ah[0][0], ah[0][1], ah[0][2], ah[0][3], aHiB + so + aOff + kb);
            ldm_x4(ah[1][0], ah[1][1], ah[1][2], ah[1][3], aHiB + so + aOff + kb + 16 * ZKW * 4);
            ldm_x4(al[0][0], al[0][1], al[0][2], al[0][3], aLoB + so + aOff + kb);
            ldm_x4(al[1][0], al[1][1], al[1][2], al[1][3], aLoB + so + aOff + kb + 16 * ZKW * 4);

            unsigned vbh0[8], vbh1[8], vbl0[8], vbl1[8];
#pragma unroll
            for (int ntp = 0; ntp < 4; ntp++) {
                unsigned r0, r1, r2, r3;
                ldm_x4(r0, r1, r2, r3, bHiB + so + bOff + kb + ntp * 16 * ZKW * 4);
                vbh0[2 * ntp] = r0; vbh1[2 * ntp] = r1;
                vbh0[2 * ntp + 1] = r2; vbh1[2 * ntp + 1] = r3;
                ldm_x4(r0, r1, r2, r3, bLoB + so + bOff + kb + ntp * 16 * ZKW * 4);
                vbl0[2 * ntp] = r0; vbl1[2 * ntp] = r1;
                vbl0[2 * ntp + 1] = r2; vbl1[2 * ntp + 1] = r3;
            }
            // pass-major MMA issue: consecutive HMMAs hit distinct accumulators
#pragma unroll
            for (int nt = 0; nt < 8; nt++)
#pragma unroll
                for (int mt = 0; mt < 2; mt++)
                    mma16(acc[mt][nt], al[mt], vbh0[nt], vbh1[nt]);
#pragma unroll
            for (int nt = 0; nt < 8; nt++)
#pragma unroll
                for (int mt = 0; mt < 2; mt++)
                    mma16(acc[mt][nt], ah[mt], vbl0[nt], vbl1[nt]);
#pragma unroll
            for (int nt = 0; nt < 8; nt++)
#pragma unroll
                for (int mt = 0; mt < 2; mt++)
                    mma16(acc[mt][nt], ah[mt], vbh0[nt], vbh1[nt]);
        }
        __syncthreads();
        cur ^= 1;
    }

#pragma unroll
    for (int mt = 0; mt < 2; mt++) {
        int r0 = m0 + wm * 32 + mt * 16 + g;
#pragma unroll
        for (int nt = 0; nt < 8; nt++) {
            int col = n0 + wn * 64 + nt * 8 + 2 * t;
            float bv0 = bias[col], bv1 = bias[col + 1];
            float2 v;
            v.x = acc[mt][nt][0] + bv0; v.y = acc[mt][nt][1] + bv1;
            *(float2*)&C[(size_t)r0 * NCAT + col] = v;
            v.x = acc[mt][nt][2] + bv0; v.y = acc[mt][nt][3] + bv1;
            *(float2*)&C[(size_t)(r0 + 8) * NCAT + col] = v;
        }
    }
}
#define ZH_SMEM_BYTES ((int)(4 * ZARR * 4))   // 81920

// ---------------------------------------------------------------------------
// Per-step fusion (R11/R15, measured-best): block-per-row, 256 threads.
// ---------------------------------------------------------------------------
__global__ void __launch_bounds__(256)
step_kernel(int t,
            const float* __restrict__ gum,
            const float* __restrict__ W2,
            const float* __restrict__ b2,
            const float* __restrict__ temp_ptr,
            const float* __restrict__ wpos,
            const float* __restrict__ F,
            const float* __restrict__ Zh,
            unsigned* __restrict__ h_hi,
            unsigned* __restrict__ h_lo,
            float* __restrict__ out_pos,
            float* __restrict__ out_states,
            float* __restrict__ out_hfinal)
{
    const int b = blockIdx.x;
    const int tid = threadIdx.x;
    const int warp = tid >> 5, lane = tid & 31;
    const size_t bt = (size_t)b * TT + t;

    __shared__ float sh_hidden[HH1];
    __shared__ float sh_logits[PP];
    __shared__ float sh_pos;

    const float* Frow = F + bt * NCAT;
    const float* Zrow = Zh + (size_t)b * NCAT;

    const int j = tid;   // 0..255 == SS
    __nv_bfloat16 hold_hi = ((const __nv_bfloat16*)h_hi)[(size_t)b * SS + j];
    __nv_bfloat16 hold_lo = ((const __nv_bfloat16*)h_lo)[(size_t)b * SS + j];
    float f_r = Frow[HH1 + j];
    float f_z = Frow[HH1 + SS + j];
    float f_n = Frow[HH1 + 2 * SS + j];
    float z_r = Zrow[HH1 + j];
    float z_z = Zrow[HH1 + SS + j];
    float z_n = Zrow[HH1 + 2 * SS + j];
    float wp_r = wpos[j];
    float wp_z = wpos[SS + j];
    float wp_n = wpos[2 * SS + j];

    float2 hf2, hz2;
    if (tid < 192) {
        hf2 = ((const float2*)Frow)[tid];
        hz2 = ((const float2*)Zrow)[tid];
    }

    float gv = 0.0f, temp = 1.0f;
    if (warp == 0) {
        temp = *temp_ptr;
        if (lane < PP) gv = gum[bt * PP + lane];
    }

    if (tid < 192) {
        float2 r;
        r.x = fmaxf(hf2.x + hz2.x, 0.0f);
        r.y = fmaxf(hf2.y + hz2.y, 0.0f);
        ((float2*)sh_hidden)[tid] = r;
    }
    __syncthreads();

    {
        const float4* h4 = (const float4*)sh_hidden;
        const float4* W2a = (const float4*)(W2 + warp * HH1);
        float s = 0.0f;
#pragma unroll
        for (int i = 0; i < 3; i++) {
            float4 w = W2a[lane + 32 * i], hh = h4[lane + 32 * i];
            s = fmaf(w.x, hh.x, s); s = fmaf(w.y, hh.y, s);
            s = fmaf(w.z, hh.z, s); s = fmaf(w.w, hh.w, s);
        }
#pragma unroll
        for (int off = 16; off > 0; off >>= 1)
            s += __shfl_xor_sync(0xffffffffu, s, off);
        if (lane == 0) sh_logits[warp] = s + b2[warp];

        if (warp < 3) {
            const float4* W2b = (const float4*)(W2 + (warp + 8) * HH1);
            float s2 = 0.0f;
#pragma unroll
            for (int i = 0; i < 3; i++) {
                float4 w = W2b[lane + 32 * i], hh = h4[lane + 32 * i];
                s2 = fmaf(w.x, hh.x, s2); s2 = fmaf(w.y, hh.y, s2);
                s2 = fmaf(w.z, hh.z, s2); s2 = fmaf(w.w, hh.w, s2);
            }
#pragma unroll
            for (int off = 16; off > 0; off >>= 1)
                s2 += __shfl_xor_sync(0xffffffffu, s2, off);
            if (lane == 0) sh_logits[warp + 8] = s2 + b2[warp + 8];
        }
    }
    __syncthreads();

    if (warp == 0) {
        float val = -INFINITY;
        if (lane < PP) val = (sh_logits[lane] + gv) / temp;
        float m = val;
#pragma unroll
        for (int off = 16; off > 0; off >>= 1)
            m = fmaxf(m, __shfl_xor_sync(0xffffffffu, m, off));
        float e = (lane < PP) ? __expf(val - m) : 0.0f;
        float s = e;
        float w = (lane < PP) ? e * (float)lane : 0.0f;
#pragma unroll
        for (int off = 16; off > 0; off >>= 1) {
            s += __shfl_xor_sync(0xffffffffu, s, off);
            w += __shfl_xor_sync(0xffffffffu, w, off);
        }
        if (lane == 0) {
            float pos = w / s;
            sh_pos = pos;
            out_pos[bt] = pos;
        }
    }
    __syncthreads();
    const float pos = sh_pos;

    float hold = __bfloat162float(hold_hi) + __bfloat162float(hold_lo);
    float gi_r = f_r + pos * wp_r;
    float gi_z = f_z + pos * wp_z;
    float gi_n = f_n + pos * wp_n;

    float r = 1.0f / (1.0f + __expf(-(gi_r + z_r)));
    float z = 1.0f / (1.0f + __expf(-(gi_z + z_z)));
    float xn = gi_n + r * z_n;
    float n = 1.0f - 2.0f / (__expf(2.0f * xn) + 1.0f);
    float hnew = (1.0f - z) * n + z * hold;

    {
        __nv_bfloat16 bh = __float2bfloat16(hnew);
        ((__nv_bfloat16*)h_hi)[(size_t)b * SS + j] = bh;
        ((__nv_bfloat16*)h_lo)[(size_t)b * SS + j] =
            __float2bfloat16(hnew - __bfloat162float(bh));
    }
    out_states[bt * SS + j] = hnew;
    if (t == TT - 1) out_hfinal[(size_t)b * SS + j] = hnew;
}

// ---------------------------------------------------------------------------
extern "C" void kernel_launch(void* const* d_in, const int* in_sizes, int n_in,
                              void* d_out, int out_size)
{
    const float* price = (const float*)d_in[0];
    const float* u     = (const float*)d_in[1];
    const float* W1    = (const float*)d_in[2];
    const float* b1    = (const float*)d_in[3];
    const float* W2    = (const float*)d_in[4];
    const float* b2    = (const float*)d_in[5];
    const float* temp  = (const float*)d_in[6];
    const float* W_ih  = (const float*)d_in[7];
    const float* b_ih  = (const float*)d_in[8];
    const float* W_hh  = (const float*)d_in[9];
    const float* b_hh  = (const float*)d_in[10];
    const float* h0    = (const float*)d_in[11];

    float* scratch = nullptr;
    cudaGetSymbolAddress((void**)&scratch, g_scratch);
    float* F      = scratch + OFF_F;
    float* Zh     = scratch + OFF_ZH;
    float* gum    = scratch + OFF_GUM;
    float* wpos   = scratch + OFF_WPOS;
    float* bf     = scratch + OFF_BF;
    float* bzh    = scratch + OFF_BZH;
    unsigned* Wfhi = (unsigned*)(scratch + OFF_WFHI);
    unsigned* Wflo = (unsigned*)(scratch + OFF_WFLO);
    unsigned* Whhi = (unsigned*)(scratch + OFF_WHHI);
    unsigned* Whlo = (unsigned*)(scratch + OFF_WHLO);
    unsigned* h_hi = (unsigned*)(scratch + OFF_HHI);
    unsigned* h_lo = (unsigned*)(scratch + OFF_HLO);

    float* out        = (float*)d_out;
    float* out_pos    = out;                                  // [B, T]
    float* out_states = out + (size_t)BB * TT;                // [B, T, S]
    float* out_hf     = out_states + (size_t)BB * TT * SS;    // [B, S]

    cudaFuncSetAttribute(gemm_zh,
                         cudaFuncAttributeMaxDynamicSharedMemorySize,
                         ZH_SMEM_BYTES);

    // 1. pack + gumbel precompute
    pack_kernel<<<(BB * SS + 255) / 256, 256>>>(W1, b1, W_ih, b_ih, W_hh, b_hh,
                                                h0, Wfhi, Wflo, Whhi, Whlo,
                                                bf, bzh, h_hi, h_lo, wpos);
    gumbel_kernel<<<(BB * TT * PP + 255) / 256, 256>>>(u, gum);

    // 2. F GEMM split: 1-pass hidden tiles + 3-pass gi tiles (ldmatrix)
    {
        dim3 grid1(3, (BB * TT) / 128);   // hidden cols 0..383
        gemm_f_1p<<<grid1, 256>>>(price, Wfhi, bf, F);
        dim3 grid3(6, (BB * TT) / 128);   // gi cols 384..1151
        gemm_f_3p<<<grid3, 256>>>(price, Wfhi, Wflo, bf, F);
    }

    // 3. sequential recurrence: cp.async + ldmatrix + pass-major Zh, step
    for (int t = 0; t < TT; t++) {
        dim3 grid(NCAT / 128, BB / 128);          // (9, 16) = 144 blocks
        gemm_zh<<<grid, 256, ZH_SMEM_BYTES>>>(h_hi, h_lo, Whhi, Whlo, bzh, Zh);
        step_kernel<<<BB, 256>>>(t, gum, W2, b2, temp, wpos,
                                 F, Zh, h_hi, h_lo,
                                 out_pos, out_states, out_hf);
    }
}